// round 5
// baseline (speedup 1.0000x reference)
#include <cuda_runtime.h>
#include <cuda_fp16.h>
#include <math.h>
#include <stdint.h>

#define NPTS 16384
#define C 512
#define H 8
#define HD 64
#define KWIN 1024
#define P (NPTS / KWIN)
#define SCALE 0.125f
#define MAX_TILES 3328

// ---------------- scratch ----------------
__device__ float g_tmp1[NPTS * C];
__device__ float g_tmp2[NPTS * C];
__device__ float g_feat1[NPTS * C];

__device__ __half g_fhi[NPTS * C];
__device__ __half g_flo[NPTS * C];
__device__ __half g_t1hi[NPTS * C];
__device__ __half g_t1lo[NPTS * C];
__device__ __half g_xhi[NPTS * C];
__device__ __half g_xlo[NPTS * C];
__device__ __half g_qkvh[NPTS * 3 * C];
__device__ __half g_obhi[NPTS * C];
__device__ __half g_oblo[NPTS * C];
__device__ __half g_yhi[NPTS * 4 * C];
__device__ __half g_ylo[NPTS * 4 * C];

#define WPOOL (27*C*C + C*C + 3*C*C + C*C + 4*C*C + 4*C*C)
__device__ __half g_wh[WPOOL];

#define OFF_CPE   0
#define OFF_LIN   (27*C*C)
#define OFF_QKV   (OFF_LIN + C*C)
#define OFF_PROJ  (OFF_QKV + 3*C*C)
#define OFF_FC1   (OFF_PROJ + C*C)
#define OFF_FC2   (OFF_FC1 + 4*C*C)

// sparse CPE bookkeeping
__device__ int g_cnt[26];
__device__ int g_cursor[26];
__device__ int g_pofs[27];
__device__ int g_ntiles;
__device__ int g_tiletap[MAX_TILES];
__device__ int2 g_plist[MAX_TILES * 128];

// ---------------- helpers ----------------
__device__ __forceinline__ uint32_t s2u(const void* p) {
    return (uint32_t)__cvta_generic_to_shared(p);
}
__device__ __forceinline__ void ldmx4(uint32_t& r0, uint32_t& r1, uint32_t& r2, uint32_t& r3,
                                      uint32_t addr) {
    asm volatile("ldmatrix.sync.aligned.m8n8.x4.shared.b16 {%0,%1,%2,%3}, [%4];"
                 : "=r"(r0), "=r"(r1), "=r"(r2), "=r"(r3) : "r"(addr));
}
__device__ __forceinline__ void ldmx4t(uint32_t& r0, uint32_t& r1, uint32_t& r2, uint32_t& r3,
                                       uint32_t addr) {
    asm volatile("ldmatrix.sync.aligned.m8n8.x4.trans.shared.b16 {%0,%1,%2,%3}, [%4];"
                 : "=r"(r0), "=r"(r1), "=r"(r2), "=r"(r3) : "r"(addr));
}
__device__ __forceinline__ void mma_f16(float* d, const uint32_t* a, uint32_t b0, uint32_t b1) {
    asm volatile("mma.sync.aligned.m16n8k16.row.col.f32.f16.f16.f32 "
                 "{%0,%1,%2,%3},{%4,%5,%6,%7},{%8,%9},{%0,%1,%2,%3};"
                 : "+f"(d[0]), "+f"(d[1]), "+f"(d[2]), "+f"(d[3])
                 : "r"(a[0]), "r"(a[1]), "r"(a[2]), "r"(a[3]), "r"(b0), "r"(b1));
}
__device__ __forceinline__ int sidx(int r, int k) {
    return r * 32 + ((((k >> 3) ^ ((r >> 1) & 3)) << 3) | (k & 7));
}
__device__ __forceinline__ int aidx(int r, int k) {
    return r * 64 + ((((k >> 3) ^ (r & 7)) << 3) | (k & 7));
}
__device__ __forceinline__ uint32_t h2u(__half2 h) { return *(uint32_t*)&h; }
__device__ __forceinline__ uint4 cvt8s(float4 f0, float4 f1) {
    __half2 a = __floats2half2_rn(f0.x, f0.y), b = __floats2half2_rn(f0.z, f0.w);
    __half2 c = __floats2half2_rn(f1.x, f1.y), d = __floats2half2_rn(f1.z, f1.w);
    return make_uint4(h2u(a), h2u(b), h2u(c), h2u(d));
}
__device__ __forceinline__ void cvt8h(float4 f0, float4 f1, uint4& hi, uint4& lo) {
    __half2 h, l;
    h = __floats2half2_rn(f0.x, f0.y);
    l = __floats2half2_rn(f0.x - __half2float(__low2half(h)), f0.y - __half2float(__high2half(h)));
    hi.x = h2u(h); lo.x = h2u(l);
    h = __floats2half2_rn(f0.z, f0.w);
    l = __floats2half2_rn(f0.z - __half2float(__low2half(h)), f0.w - __half2float(__high2half(h)));
    hi.y = h2u(h); lo.y = h2u(l);
    h = __floats2half2_rn(f1.x, f1.y);
    l = __floats2half2_rn(f1.x - __half2float(__low2half(h)), f1.y - __half2float(__high2half(h)));
    hi.z = h2u(h); lo.z = h2u(l);
    h = __floats2half2_rn(f1.z, f1.w);
    l = __floats2half2_rn(f1.z - __half2float(__low2half(h)), f1.w - __half2float(__high2half(h)));
    hi.w = h2u(h); lo.w = h2u(l);
}

// GEMM smem: stage = Ahi(4096) + Alo(4096) + B(4096) halves
#define ST_STRIDE 12288
#define SM_AHI 0
#define SM_ALO 4096
#define SM_B   8192
#define SMEM_BYTES (2 * ST_STRIDE * 2)

// ---------------- fused prepass ----------------
// segments: [0,5120) weight fp16; [5120,9216) feat split; [9216,10880) plist zero; [10880] counters
__global__ void prep_all(const float* __restrict__ w_cpe, const float* __restrict__ w_lin,
                         const float* __restrict__ w_qkv, const float* __restrict__ w_proj,
                         const float* __restrict__ w_fc1, const float* __restrict__ w_fc2,
                         const float* __restrict__ feat)
{
    const int b = blockIdx.x, t = threadIdx.x;
    if (b < 5120) {
        const int i = b * 2048 + t * 8;
        const float* s; int o;
        if (i < OFF_LIN)       { s = w_cpe;  o = i; }
        else if (i < OFF_QKV)  { s = w_lin;  o = i - OFF_LIN; }
        else if (i < OFF_PROJ) { s = w_qkv;  o = i - OFF_QKV; }
        else if (i < OFF_FC1)  { s = w_proj; o = i - OFF_PROJ; }
        else if (i < OFF_FC2)  { s = w_fc1;  o = i - OFF_FC1; }
        else                   { s = w_fc2;  o = i - OFF_FC2; }
        float4 f0 = *(const float4*)(s + o);
        float4 f1 = *(const float4*)(s + o + 4);
        *(uint4*)(g_wh + i) = cvt8s(f0, f1);
    } else if (b < 9216) {
        const int i = (b - 5120) * 2048 + t * 8;
        float4 f0 = *(const float4*)(feat + i);
        float4 f1 = *(const float4*)(feat + i + 4);
        uint4 h, l; cvt8h(f0, f1, h, l);
        *(uint4*)(g_fhi + i) = h;
        *(uint4*)(g_flo + i) = l;
    } else if (b < 10880) {
        const int i = (b - 9216) * 256 + t;
        g_plist[i] = make_int2(-1, -1);
    } else {
        if (t < 26) { g_cnt[t] = 0; g_cursor[t] = 0; }
    }
}

__global__ void split_k(const float* __restrict__ src, __half* __restrict__ hi,
                        __half* __restrict__ lo)
{
    const int i = (blockIdx.x * blockDim.x + threadIdx.x) * 8;
    float4 f0 = *(const float4*)(src + i);
    float4 f1 = *(const float4*)(src + i + 4);
    uint4 h, l; cvt8h(f0, f1, h, l);
    *(uint4*)(hi + i) = h;
    *(uint4*)(lo + i) = l;
}

// ---------------- sparse CPE prepass ----------------
__global__ void prep_count(const int* __restrict__ nbr)
{
    int s = blockIdx.y, kk = (s < 13) ? s : s + 1;
    int n = blockIdx.x * blockDim.x + threadIdx.x;
    bool v = __ldg(nbr + (size_t)n * 27 + kk) >= 0;
    unsigned m = __ballot_sync(0xffffffffu, v);
    if ((threadIdx.x & 31) == 0 && m) atomicAdd(&g_cnt[s], __popc(m));
}
__global__ void prep_scan()
{
    __shared__ int sofs[27];
    if (threadIdx.x == 0) {
        int o = 0;
        for (int s = 0; s < 26; ++s) {
            sofs[s] = o; g_pofs[s] = o;
            o += ((g_cnt[s] + 127) >> 7) << 7;
        }
        sofs[26] = o; g_pofs[26] = o; g_ntiles = o >> 7;
    }
    __syncthreads();
    int nt = sofs[26] >> 7;
    for (int tile = threadIdx.x; tile < nt; tile += blockDim.x) {
        int pos = tile << 7;
        int s = 0;
        while (!(pos >= sofs[s] && pos < sofs[s + 1])) ++s;
        g_tiletap[tile] = (s < 13) ? s : s + 1;
    }
}
__global__ void prep_fill(const int* __restrict__ nbr)
{
    int s = blockIdx.y, kk = (s < 13) ? s : s + 1;
    int n = blockIdx.x * blockDim.x + threadIdx.x;
    int j = __ldg(nbr + (size_t)n * 27 + kk);
    bool v = j >= 0;
    unsigned m = __ballot_sync(0xffffffffu, v);
    int base = 0;
    if ((threadIdx.x & 31) == 0 && m) base = atomicAdd(&g_cursor[s], __popc(m));
    base = __shfl_sync(0xffffffffu, base, 0);
    if (v) {
        int pos = base + __popc(m & ((1u << (threadIdx.x & 31)) - 1));
        g_plist[g_pofs[s] + pos] = make_int2(n, j);
    }
}

// ---------------- core mma on one resident chunk ----------------
__device__ __forceinline__ void mma_chunk(const __half* sbuf, int wm, int wn, int lane,
                                          float acc[4][4][4])
{
#pragma unroll
    for (int kk16 = 0; kk16 < 2; ++kk16) {
        const int kc = kk16 * 2 + (lane >> 4);
        uint32_t ah[4][4], al[4][4], bb[2][4];
#pragma unroll
        for (int mf = 0; mf < 4; ++mf) {
            const int row = wm * 64 + mf * 16 + (lane & 15);
            const int off = sidx(row, kc * 8);
            ldmx4(ah[mf][0], ah[mf][1], ah[mf][2], ah[mf][3], s2u(sbuf + SM_AHI + off));
            ldmx4(al[mf][0], al[mf][1], al[mf][2], al[mf][3], s2u(sbuf + SM_ALO + off));
        }
#pragma unroll
        for (int np = 0; np < 2; ++np) {
            const int row = wn * 32 + np * 16 + (lane & 15);
            const int off = sidx(row, kc * 8);
            ldmx4(bb[np][0], bb[np][1], bb[np][2], bb[np][3], s2u(sbuf + SM_B + off));
        }
#pragma unroll
        for (int mf = 0; mf < 4; ++mf) {
#pragma unroll
            for (int nf = 0; nf < 4; ++nf) {
                const int pr = nf >> 1, sb = nf & 1;
                mma_f16(acc[mf][nf], ah[mf], bb[pr][sb], bb[pr][sb + 2]);
                mma_f16(acc[mf][nf], al[mf], bb[pr][sb], bb[pr][sb + 2]);
            }
        }
    }
}

// ---------------- epilogue ----------------
template <bool GELU, bool RES, bool WF32, bool WHI, bool WLO>
__device__ __forceinline__ void epilogue(float acc[4][4][4], int bm, int bn, int Nn,
                                         int wm, int wn, int lane,
                                         const float* bias, const float* res,
                                         float* outf, __half* outhi, __half* outlo)
{
#pragma unroll
    for (int mf = 0; mf < 4; ++mf) {
#pragma unroll
        for (int nf = 0; nf < 4; ++nf) {
            const int n0 = bn + wn * 32 + nf * 8 + 2 * (lane & 3);
            const float b0 = __ldg(bias + n0), b1 = __ldg(bias + n0 + 1);
#pragma unroll
            for (int half = 0; half < 2; ++half) {
                const int m = bm + wm * 64 + mf * 16 + (lane >> 2) + half * 8;
                float v0 = acc[mf][nf][half * 2 + 0] + b0;
                float v1 = acc[mf][nf][half * 2 + 1] + b1;
                if (GELU) {
                    v0 = 0.5f * v0 * (1.f + erff(v0 * 0.70710678118f));
                    v1 = 0.5f * v1 * (1.f + erff(v1 * 0.70710678118f));
                }
                if (RES) {
                    float2 r2 = *(const float2*)(res + (size_t)m * Nn + n0);
                    v0 += r2.x; v1 += r2.y;
                }
                if (WF32)
                    *(float2*)(outf + (size_t)m * Nn + n0) = make_float2(v0, v1);
                if (WHI) {
                    __half2 hh = __floats2half2_rn(v0, v1);
                    *(uint32_t*)(outhi + (size_t)m * Nn + n0) = h2u(hh);
                    if (WLO) {
                        __half2 ll = __floats2half2_rn(
                            v0 - __half2float(__low2half(hh)),
                            v1 - __half2float(__high2half(hh)));
                        *(uint32_t*)(outlo + (size_t)m * Nn + n0) = h2u(ll);
                    }
                }
            }
        }
    }
}

// ---------------- dense GEMM on pre-split A ----------------
template <bool GELU, bool RES, bool WF32, bool WHI, bool WLO>
__global__ void __launch_bounds__(256)
tc_gemm(const __half* __restrict__ Ahi, const __half* __restrict__ Alo,
        const __half* __restrict__ Bh,
        const float* __restrict__ bias, const float* __restrict__ res,
        float* __restrict__ outf, __half* __restrict__ outhi, __half* __restrict__ outlo,
        int Nn, int Kk)
{
    extern __shared__ __align__(16) __half smem[];
    const int t = threadIdx.x, lane = t & 31, warp = t >> 5;
    const int wm = warp >> 2, wn = warp & 3;
    const int bm = blockIdx.y * 128, bn = blockIdx.x * 128;

    float acc[4][4][4];
#pragma unroll
    for (int a = 0; a < 4; ++a)
#pragma unroll
        for (int b = 0; b < 4; ++b)
#pragma unroll
            for (int c = 0; c < 4; ++c) acc[a][b][c] = 0.f;

    const int nchunk = Kk / 32;
    const int r0 = t >> 2, c0 = t & 3;
    const int r1 = (t + 256) >> 2;
    const size_t a0 = (size_t)(bm + r0) * Kk + c0 * 8;
    const size_t a1 = (size_t)(bm + r1) * Kk + c0 * 8;
    const size_t b0 = (size_t)(bn + r0) * Kk + c0 * 8;
    const size_t b1 = (size_t)(bn + r1) * Kk + c0 * 8;

    // preload chunk 0
    *(uint4*)(smem + SM_AHI + sidx(r0, c0 * 8)) = *(const uint4*)(Ahi + a0);
    *(uint4*)(smem + SM_ALO + sidx(r0, c0 * 8)) = *(const uint4*)(Alo + a0);
    *(uint4*)(smem + SM_AHI + sidx(r1, c0 * 8)) = *(const uint4*)(Ahi + a1);
    *(uint4*)(smem + SM_ALO + sidx(r1, c0 * 8)) = *(const uint4*)(Alo + a1);
    *(uint4*)(smem + SM_B + sidx(r0, c0 * 8)) = *(const uint4*)(Bh + b0);
    *(uint4*)(smem + SM_B + sidx(r1, c0 * 8)) = *(const uint4*)(Bh + b1);
    __syncthreads();

    for (int chunk = 0; chunk < nchunk; ++chunk) {
        const __half* cur = smem + (chunk & 1) * ST_STRIDE;
        __half* nxt = smem + ((chunk + 1) & 1) * ST_STRIDE;
        uint4 pah0, pal0, pah1, pal1, pb0, pb1;
        const bool more = (chunk + 1 < nchunk);
        if (more) {
            const int kb = (chunk + 1) * 32;
            pah0 = *(const uint4*)(Ahi + a0 + kb); pal0 = *(const uint4*)(Alo + a0 + kb);
            pah1 = *(const uint4*)(Ahi + a1 + kb); pal1 = *(const uint4*)(Alo + a1 + kb);
            pb0 = *(const uint4*)(Bh + b0 + kb);   pb1 = *(const uint4*)(Bh + b1 + kb);
        }
        mma_chunk(cur, wm, wn, lane, acc);
        __syncthreads();
        if (more) {
            *(uint4*)(nxt + SM_AHI + sidx(r0, c0 * 8)) = pah0;
            *(uint4*)(nxt + SM_ALO + sidx(r0, c0 * 8)) = pal0;
            *(uint4*)(nxt + SM_AHI + sidx(r1, c0 * 8)) = pah1;
            *(uint4*)(nxt + SM_ALO + sidx(r1, c0 * 8)) = pal1;
            *(uint4*)(nxt + SM_B + sidx(r0, c0 * 8)) = pb0;
            *(uint4*)(nxt + SM_B + sidx(r1, c0 * 8)) = pb1;
        }
        __syncthreads();
    }
    epilogue<GELU, RES, WF32, WHI, WLO>(acc, bm, bn, Nn, wm, wn, lane, bias, res,
                                        outf, outhi, outlo);
}

// ---------------- sparse CPE GEMM: persistent, scatter-accumulate ----------------
__global__ void __launch_bounds__(256)
cpe_sparse(const __half* __restrict__ fhi, const __half* __restrict__ flo,
           const __half* __restrict__ W, float* __restrict__ out)
{
    extern __shared__ __align__(16) __half smem[];
    __shared__ int sn[128];
    const int t = threadIdx.x, lane = t & 31, warp = t >> 5;
    const int wm = warp >> 2, wn = warp & 3;
    const int bn = blockIdx.x * 128;
    const int r0 = t >> 2, c0 = t & 3;
    const int r1 = (t + 256) >> 2;

    for (int tile = blockIdx.y; tile < g_ntiles; tile += gridDim.y) {
        __syncthreads();
        const int kk = g_tiletap[tile];
        const __half* Wk = W + (size_t)kk * C * C;
        const int2* pl = g_plist + (size_t)tile * 128;
        if (t < 128) sn[t] = pl[t].x;

        float acc[4][4][4];
#pragma unroll
        for (int a = 0; a < 4; ++a)
#pragma unroll
            for (int b = 0; b < 4; ++b)
#pragma unroll
                for (int c = 0; c < 4; ++c) acc[a][b][c] = 0.f;

        const int j0 = __ldg(&pl[r0].y), j1 = __ldg(&pl[r1].y);
        const size_t f0 = (size_t)(j0 < 0 ? 0 : j0) * C + c0 * 8;
        const size_t f1 = (size_t)(j1 < 0 ? 0 : j1) * C + c0 * 8;
        const uint4 zz = make_uint4(0, 0, 0, 0);

        // preload chunk 0
        *(uint4*)(smem + SM_AHI + sidx(r0, c0 * 8)) = (j0 >= 0) ? *(const uint4*)(fhi + f0) : zz;
        *(uint4*)(smem + SM_ALO + sidx(r0, c0 * 8)) = (j0 >= 0) ? *(const uint4*)(flo + f0) : zz;
        *(uint4*)(smem + SM_AHI + sidx(r1, c0 * 8)) = (j1 >= 0) ? *(const uint4*)(fhi + f1) : zz;
        *(uint4*)(smem + SM_ALO + sidx(r1, c0 * 8)) = (j1 >= 0) ? *(const uint4*)(flo + f1) : zz;
        *(uint4*)(smem + SM_B + sidx(r0, c0 * 8)) = *(const uint4*)(Wk + (size_t)(bn + r0) * C + c0 * 8);
        *(uint4*)(smem + SM_B + sidx(r1, c0 * 8)) = *(const uint4*)(Wk + (size_t)(bn + r1) * C + c0 * 8);
        __syncthreads();

        const int nchunk = C / 32;
        for (int chunk = 0; chunk < nchunk; ++chunk) {
            const __half* cur = smem + (chunk & 1) * ST_STRIDE;
            __half* nxt = smem + ((chunk + 1) & 1) * ST_STRIDE;
            uint4 pah0, pal0, pah1, pal1, pb0, pb1;
            const bool more = (chunk + 1 < nchunk);
            if (more) {
                const int kb = (chunk + 1) * 32;
                pah0 = (j0 >= 0) ? *(const uint4*)(fhi + f0 + kb) : zz;
                pal0 = (j0 >= 0) ? *(const uint4*)(flo + f0 + kb) : zz;
                pah1 = (j1 >= 0) ? *(const uint4*)(fhi + f1 + kb) : zz;
                pal1 = (j1 >= 0) ? *(const uint4*)(flo + f1 + kb) : zz;
                pb0 = *(const uint4*)(Wk + (size_t)(bn + r0) * C + kb + c0 * 8);
                pb1 = *(const uint4*)(Wk + (size_t)(bn + r1) * C + kb + c0 * 8);
            }
            mma_chunk(cur, wm, wn, lane, acc);
            __syncthreads();
            if (more) {
                *(uint4*)(nxt + SM_AHI + sidx(r0, c0 * 8)) = pah0;
                *(uint4*)(nxt + SM_ALO + sidx(r0, c0 * 8)) = pal0;
                *(uint4*)(nxt + SM_AHI + sidx(r1, c0 * 8)) = pah1;
                *(uint4*)(nxt + SM_ALO + sidx(r1, c0 * 8)) = pal1;
                *(uint4*)(nxt + SM_B + sidx(r0, c0 * 8)) = pb0;
                *(uint4*)(nxt + SM_B + sidx(r1, c0 * 8)) = pb1;
            }
            __syncthreads();
        }
        // scatter-accumulate
#pragma unroll
        for (int mf = 0; mf < 4; ++mf) {
#pragma unroll
            for (int half = 0; half < 2; ++half) {
                const int ml = wm * 64 + mf * 16 + (lane >> 2) + half * 8;
                const int n = sn[ml];
                if (n < 0) continue;
                float* dst = out + (size_t)n * C;
#pragma unroll
                for (int nf = 0; nf < 4; ++nf) {
                    const int n0 = bn + wn * 32 + nf * 8 + 2 * (lane & 3);
                    atomicAdd(dst + n0,     acc[mf][nf][half * 2 + 0]);
                    atomicAdd(dst + n0 + 1, acc[mf][nf][half * 2 + 1]);
                }
            }
        }
    }
}

// ---------------- LayerNorm ----------------
template <bool RES, bool WSPLIT>
__global__ void ln_kernel(const float* __restrict__ in, const float* __restrict__ res,
                          const float* __restrict__ gam, const float* __restrict__ bet,
                          float* __restrict__ outf, __half* __restrict__ outhi,
                          __half* __restrict__ outlo)
{
    const int n = blockIdx.x;
    const int t = threadIdx.x;
    float4 v = *(const float4*)(in + (size_t)n * C + t * 4);
    float s1 = v.x + v.y + v.z + v.w;
    float s2 = v.x * v.x + v.y * v.y + v.z * v.z + v.w * v.w;
#pragma unroll
    for (int o = 16; o; o >>= 1) {
        s1 += __shfl_xor_sync(0xffffffffu, s1, o);
        s2 += __shfl_xor_sync(0xffffffffu, s2, o);
    }
    __shared__ float sh1[4], sh2[4];
    const int wid = t >> 5, lane = t & 31;
    if (lane == 0) { sh1[wid] = s1; sh2[wid] = s2; }
    __syncthreads();
    float S1 = sh1[0] + sh1[1] + sh1[2] + sh1[3];
    float S2 = sh2[0] + sh2[1] + sh2[2] + sh2[3];
    float mean = S1 * (1.f / C);
    float var = S2 * (1.f / C) - mean * mean;
    float inv = rsqrtf(var + 1e-5f);
    float4 g4 = *(const float4*)(gam + t * 4);
    float4 b4 = *(const float4*)(bet + t * 4);
    float4 o4;
    o4.x = (v.x - mean) * inv * g4.x + b4.x;
    o4.y = (v.y - mean) * inv * g4.y + b4.y;
    o4.z = (v.z - mean) * inv * g4.z + b4.z;
    o4.w = (v.w - mean) * inv * g4.w + b4.w;
    if (RES) {
        float4 r4 = *(const float4*)(res + (size_t)n * C + t * 4);
        o4.x += r4.x; o4.y += r4.y; o4.z += r4.z; o4.w += r4.w;
    }
    if (WSPLIT) {
        __half2 h0 = __floats2half2_rn(o4.x, o4.y);
        __half2 h1 = __floats2half2_rn(o4.z, o4.w);
        __half2 l0 = __floats2half2_rn(o4.x - __half2float(__low2half(h0)),
                                       o4.y - __half2float(__high2half(h0)));
        __half2 l1 = __floats2half2_rn(o4.z - __half2float(__low2half(h1)),
                                       o4.w - __half2float(__high2half(h1)));
        *(uint2*)(outhi + (size_t)n * C + t * 4) = make_uint2(h2u(h0), h2u(h1));
        *(uint2*)(outlo + (size_t)n * C + t * 4) = make_uint2(h2u(l0), h2u(l1));
    } else {
        *(float4*)(outf + (size_t)n * C + t * 4) = o4;
    }
}

// ---------------- tensor-core flash attention (fp16 in, split out) ----------------
#define ATT_Q 0
#define ATT_K 8192
#define ATT_V 16384
#define ATT_SMEM (24576 * 2)

__global__ void __launch_bounds__(256)
attn_kernel(const __half* __restrict__ qkvh, const int* __restrict__ order,
            __half* __restrict__ obhi, __half* __restrict__ oblo)
{
    extern __shared__ __align__(16) __half asmem[];
    const int t = threadIdx.x, lane = t & 31, warp = t >> 5;
    const int qt = blockIdx.x, h = blockIdx.y, p = blockIdx.z;
    const int qbase = p * KWIN + qt * 128;
    const __half2 hsc = __floats2half2_rn(SCALE, SCALE);

    // load Q (scaled, exact x0.125)
    for (int u = t; u < 1024; u += 256) {
        int r = u >> 3, c = u & 7;
        int n = __ldg(order + qbase + r);
        uint4 q = *(const uint4*)(qkvh + (size_t)n * (3 * C) + h * HD + c * 8);
        __half2* qh = (__half2*)&q;
        qh[0] = __hmul2(qh[0], hsc); qh[1] = __hmul2(qh[1], hsc);
        qh[2] = __hmul2(qh[2], hsc); qh[3] = __hmul2(qh[3], hsc);
        *(uint4*)(asmem + ATT_Q + aidx(r, c * 8)) = q;
    }

    float mrow[2] = {-1e30f, -1e30f}, lrow[2] = {0.f, 0.f};
    float oacc[8][4];
#pragma unroll
    for (int j = 0; j < 8; ++j)
#pragma unroll
        for (int c = 0; c < 4; ++c) oacc[j][c] = 0.f;

    for (int kt = 0; kt < KWIN / 128; ++kt) {
        __syncthreads();
        for (int u = t; u < 1024; u += 256) {
            int r = u >> 3, c = u & 7;
            int n = __ldg(order + p * KWIN + kt * 128 + r);
            *(uint4*)(asmem + ATT_K + aidx(r, c * 8)) =
                *(const uint4*)(qkvh + (size_t)n * (3 * C) + C + h * HD + c * 8);
            *(uint4*)(asmem + ATT_V + aidx(r, c * 8)) =
                *(const uint4*)(qkvh + (size_t)n * (3 * C) + 2 * C + h * HD + c * 8);
        }
        __syncthreads();

        float s[16][4];
#pragma unroll
        for (int j = 0; j < 16; ++j)
#pragma unroll
            for (int c = 0; c < 4; ++c) s[j][c] = 0.f;
#pragma unroll
        for (int kk = 0; kk < 4; ++kk) {
            const int kc = kk * 2 + (lane >> 4);
            uint32_t a[4];
            {
                int row = warp * 16 + (lane & 15);
                ldmx4(a[0], a[1], a[2], a[3], s2u(asmem + ATT_Q + aidx(row, kc * 8)));
            }
#pragma unroll
            for (int np = 0; np < 8; ++np) {
                uint32_t b[4];
                int row = np * 16 + (lane & 15);
                ldmx4(b[0], b[1], b[2], b[3], s2u(asmem + ATT_K + aidx(row, kc * 8)));
                mma_f16(s[np * 2 + 0], a, b[0], b[2]);
                mma_f16(s[np * 2 + 1], a, b[1], b[3]);
            }
        }

        uint32_t ph[16][2];
#pragma unroll
        for (int half = 0; half < 2; ++half) {
            float mx = mrow[half];
#pragma unroll
            for (int j = 0; j < 16; ++j)
                mx = fmaxf(mx, fmaxf(s[j][half * 2], s[j][half * 2 + 1]));
            mx = fmaxf(mx, __shfl_xor_sync(0xffffffffu, mx, 1));
            mx = fmaxf(mx, __shfl_xor_sync(0xffffffffu, mx, 2));
            const float alpha = __expf(mrow[half] - mx);
            float sum = 0.f;
#pragma unroll
            for (int j = 0; j < 16; ++j) {
                __half2 e = h2exp2(__floats2half2_rn(
                    (s[j][half * 2] - mx) * 1.44269504f,
                    (s[j][half * 2 + 1] - mx) * 1.44269504f));
                ph[j][half] = h2u(e);
                float2 f = __half22float2(e);
                sum += f.x + f.y;
            }
            sum += __shfl_xor_sync(0xffffffffu, sum, 1);
            sum += __shfl_xor_sync(0xffffffffu, sum, 2);
            lrow[half] = lrow[half] * alpha + sum;
            mrow[half] = mx;
#pragma unroll
            for (int j = 0; j < 8; ++j) {
                oacc[j][half * 2] *= alpha;
                oacc[j][half * 2 + 1] *= alpha;
            }
        }

#pragma unroll
        for (int kc = 0; kc < 8; ++kc) {
            uint32_t pa[4] = { ph[kc * 2][0], ph[kc * 2][1], ph[kc * 2 + 1][0], ph[kc * 2 + 1][1] };
#pragma unroll
            for (int dp = 0; dp < 4; ++dp) {
                uint32_t b[4];
                int row = kc * 16 + ((lane >> 3) & 1) * 8 + (lane & 7);
                int col = dp * 16 + (lane >> 4) * 8;
                ldmx4t(b[0], b[1], b[2], b[3], s2u(asmem + ATT_V + aidx(row, col)));
                mma_f16(oacc[dp * 2 + 0], pa, b[0], b[1]);
                mma_f16(oacc[dp * 2 + 1], pa, b[2], b[3]);
            }
        }
    }

#pragma unroll
    for (int half = 0; half < 2; ++half) {
        const float inv = 1.f / lrow[half];
        const int r = warp * 16 + (lane >> 2) + half * 8;
        const int n = __ldg(order + qbase + r);
        __half* dh = obhi + (size_t)n * C + h * HD;
        __half* dl = oblo + (size_t)n * C + h * HD;
#pragma unroll
        for (int j = 0; j < 8; ++j) {
            const int d0 = j * 8 + 2 * (lane & 3);
            float v0 = oacc[j][half * 2] * inv;
            float v1 = oacc[j][half * 2 + 1] * inv;
            __half2 hh = __floats2half2_rn(v0, v1);
            __half2 ll = __floats2half2_rn(v0 - __half2float(__low2half(hh)),
                                           v1 - __half2float(__high2half(hh)));
            *(uint32_t*)(dh + d0) = h2u(hh);
            *(uint32_t*)(dl + d0) = h2u(ll);
        }
    }
}

// ---------------- launch ----------------
extern "C" void kernel_launch(void* const* d_in, const int* in_sizes, int n_in,
                              void* d_out, int out_size)
{
    const float* feat      = (const float*)d_in[0];
    const int*   nbr       = (const int*)d_in[1];
    const int*   order     = (const int*)d_in[2];
    const float* cpe_w     = (const float*)d_in[3];
    const float* cpe_b     = (const float*)d_in[4];
    const float* cpe_lin_w = (const float*)d_in[5];
    const float* cpe_lin_b = (const float*)d_in[6];
    const float* cpe_ln_g  = (const float*)d_in[7];
    const float* cpe_ln_b  = (const float*)d_in[8];
    const float* ln1_g     = (const float*)d_in[9];
    const float* ln1_b     = (const float*)d_in[10];
    const float* qkv_w     = (const float*)d_in[11];
    const float* qkv_b     = (const float*)d_in[12];
    const float* proj_w    = (const float*)d_in[13];
    const float* proj_b    = (const float*)d_in[14];
    const float* ln2_g     = (const float*)d_in[15];
    const float* ln2_b     = (const float*)d_in[16];
    const float* fc1_w     = (const float*)d_in[17];
    const float* fc1_b     = (const float*)d_in[18];
    const float* fc2_w     = (const float*)d_in[19];
    const float* fc2_b     = (const float*)d_in[20];
    float* out = (float*)d_out;

    float *tmp1, *tmp2, *feat1;
    __half *wh, *fhi, *flo, *t1hi, *t1lo, *xhi, *xlo, *qkvh, *obhi, *oblo, *yhi, *ylo;
    cudaGetSymbolAddress((void**)&tmp1,  g_tmp1);
    cudaGetSymbolAddress((void**)&tmp2,  g_tmp2);
    cudaGetSymbolAddress((void**)&feat1, g_feat1);
    cudaGetSymbolAddress((void**)&wh,    g_wh);
    cudaGetSymbolAddress((void**)&fhi,   g_fhi);
    cudaGetSymbolAddress((void**)&flo,   g_flo);
    cudaGetSymbolAddress((void**)&t1hi,  g_t1hi);
    cudaGetSymbolAddress((void**)&t1lo,  g_t1lo);
    cudaGetSymbolAddress((void**)&xhi,   g_xhi);
    cudaGetSymbolAddress((void**)&xlo,   g_xlo);
    cudaGetSymbolAddress((void**)&qkvh,  g_qkvh);
    cudaGetSymbolAddress((void**)&obhi,  g_obhi);
    cudaGetSymbolAddress((void**)&oblo,  g_oblo);
    cudaGetSymbolAddress((void**)&yhi,   g_yhi);
    cudaGetSymbolAddress((void**)&ylo,   g_ylo);

    cudaFuncSetAttribute(tc_gemm<false,false,true,false,false>, cudaFuncAttributeMaxDynamicSharedMemorySize, SMEM_BYTES);
    cudaFuncSetAttribute(tc_gemm<false,false,false,true,false>, cudaFuncAttributeMaxDynamicSharedMemorySize, SMEM_BYTES);
    cudaFuncSetAttribute(tc_gemm<false,true,true,false,false>,  cudaFuncAttributeMaxDynamicSharedMemorySize, SMEM_BYTES);
    cudaFuncSetAttribute(tc_gemm<true,false,false,true,true>,   cudaFuncAttributeMaxDynamicSharedMemorySize, SMEM_BYTES);
    cudaFuncSetAttribute(cpe_sparse,  cudaFuncAttributeMaxDynamicSharedMemorySize, SMEM_BYTES);
    cudaFuncSetAttribute(attn_kernel, cudaFuncAttributeMaxDynamicSharedMemorySize, ATT_SMEM);

    // 1) fused prepass: weight fp16, feat split, plist/counter zero
    prep_all<<<10881, 256>>>(cpe_w, cpe_lin_w, qkv_w, proj_w, fc1_w, fc2_w, feat);
    // 2) sparse CPE prepass
    prep_count<<<dim3(NPTS / 256, 26), 256>>>(nbr);
    prep_scan<<<1, 128>>>();
    prep_fill<<<dim3(NPTS / 256, 26), 256>>>(nbr);

    const int MB = NPTS / 128;
    // 3) CPE center tap dense (writes bias term), then sparse taps scatter-add
    tc_gemm<false,false,true,false,false><<<dim3(C/128, MB), 256, SMEM_BYTES>>>(
        fhi, flo, wh + OFF_CPE + (size_t)13*C*C, cpe_b, nullptr, tmp1, nullptr, nullptr, C, C);
    cpe_sparse<<<dim3(C/128, 128), 256, SMEM_BYTES>>>(fhi, flo, wh + OFF_CPE, tmp1);
    // 4) split tmp1 for cpe_lin
    split_k<<<NPTS * C / 2048, 256>>>(tmp1, t1hi, t1lo);
    // 5) cpe_lin -> tmp2 fp32
    tc_gemm<false,false,true,false,false><<<dim3(C/128, MB), 256, SMEM_BYTES>>>(
        t1hi, t1lo, wh + OFF_LIN, cpe_lin_b, nullptr, tmp2, nullptr, nullptr, C, C);
    // 6) feat1 = feat + LN(tmp2)
    ln_kernel<true,false><<<NPTS, 128>>>(tmp2, feat, cpe_ln_g, cpe_ln_b, feat1, nullptr, nullptr);
    // 7) x = LN(feat1) split
    ln_kernel<false,true><<<NPTS, 128>>>(feat1, nullptr, ln1_g, ln1_b, nullptr, xhi, xlo);
    // 8) qkv (fp16 out only)
    tc_gemm<false,false,false,true,false><<<dim3(3*C/128, MB), 256, SMEM_BYTES>>>(
        xhi, xlo, wh + OFF_QKV, qkv_b, nullptr, nullptr, qkvh, nullptr, 3*C, C);
    // 9) attention -> ob split
    attn_kernel<<<dim3(KWIN/128, H, P), 256, ATT_SMEM>>>(qkvh, order, obhi, oblo);
    // 10) feat2 = feat1 + proj(ob) -> tmp1 fp32
    tc_gemm<false,true,true,false,false><<<dim3(C/128, MB), 256, SMEM_BYTES>>>(
        obhi, oblo, wh + OFF_PROJ, proj_b, feat1, tmp1, nullptr, nullptr, C, C);
    // 11) x = LN(feat2) split
    ln_kernel<false,true><<<NPTS, 128>>>(tmp1, nullptr, ln2_g, ln2_b, nullptr, xhi, xlo);
    // 12) y = gelu(fc1(x)) split out
    tc_gemm<true,false,false,true,true><<<dim3(4*C/128, MB), 256, SMEM_BYTES>>>(
        xhi, xlo, wh + OFF_FC1, fc1_b, nullptr, nullptr, yhi, ylo, 4*C, C);
    // 13) out = feat2 + fc2(y)
    tc_gemm<false,true,true,false,false><<<dim3(C/128, MB), 256, SMEM_BYTES>>>(
        yhi, ylo, wh + OFF_FC2, fc2_b, tmp1, out, nullptr, nullptr, C, 4*C);
}

// round 6
// speedup vs baseline: 1.4072x; 1.4072x over previous
#include <cuda_runtime.h>
#include <cuda_fp16.h>
#include <math.h>
#include <stdint.h>

#define NPTS 16384
#define C 512
#define H 8
#define HD 64
#define KWIN 1024
#define P (NPTS / KWIN)
#define SCALE 0.125f
#define MAX_TILES 3328

// ---------------- scratch ----------------
__device__ float g_tmp1[NPTS * C];
__device__ float g_tmp2[NPTS * C];
__device__ float g_feat1[NPTS * C];

__device__ __half g_fhi[NPTS * C];
__device__ __half g_flo[NPTS * C];
__device__ __half g_t1hi[NPTS * C];
__device__ __half g_xhi[NPTS * C];
__device__ __half g_qkvh[NPTS * 3 * C];
__device__ __half g_obhi[NPTS * C];
__device__ __half g_yhi[NPTS * 4 * C];

#define WPOOL (27*C*C + C*C + 3*C*C + C*C + 4*C*C + 4*C*C)
__device__ __half g_wh[WPOOL];

#define OFF_CPE   0
#define OFF_LIN   (27*C*C)
#define OFF_QKV   (OFF_LIN + C*C)
#define OFF_PROJ  (OFF_QKV + 3*C*C)
#define OFF_FC1   (OFF_PROJ + C*C)
#define OFF_FC2   (OFF_FC1 + 4*C*C)

// sparse CPE bookkeeping
__device__ int g_cnt[26];
__device__ int g_cursor[26];
__device__ int g_pofs[27];
__device__ int g_ntiles;
__device__ int g_tiletap[MAX_TILES];
__device__ int2 g_plist[MAX_TILES * 128];

// ---------------- helpers ----------------
__device__ __forceinline__ uint32_t s2u(const void* p) {
    return (uint32_t)__cvta_generic_to_shared(p);
}
__device__ __forceinline__ void ldmx4(uint32_t& r0, uint32_t& r1, uint32_t& r2, uint32_t& r3,
                                      uint32_t addr) {
    asm volatile("ldmatrix.sync.aligned.m8n8.x4.shared.b16 {%0,%1,%2,%3}, [%4];"
                 : "=r"(r0), "=r"(r1), "=r"(r2), "=r"(r3) : "r"(addr));
}
__device__ __forceinline__ void ldmx4t(uint32_t& r0, uint32_t& r1, uint32_t& r2, uint32_t& r3,
                                       uint32_t addr) {
    asm volatile("ldmatrix.sync.aligned.m8n8.x4.trans.shared.b16 {%0,%1,%2,%3}, [%4];"
                 : "=r"(r0), "=r"(r1), "=r"(r2), "=r"(r3) : "r"(addr));
}
__device__ __forceinline__ void mma_f16(float* d, const uint32_t* a, uint32_t b0, uint32_t b1) {
    asm volatile("mma.sync.aligned.m16n8k16.row.col.f32.f16.f16.f32 "
                 "{%0,%1,%2,%3},{%4,%5,%6,%7},{%8,%9},{%0,%1,%2,%3};"
                 : "+f"(d[0]), "+f"(d[1]), "+f"(d[2]), "+f"(d[3])
                 : "r"(a[0]), "r"(a[1]), "r"(a[2]), "r"(a[3]), "r"(b0), "r"(b1));
}
__device__ __forceinline__ int sidx(int r, int k) {
    return r * 32 + ((((k >> 3) ^ ((r >> 1) & 3)) << 3) | (k & 7));
}
__device__ __forceinline__ int aidx(int r, int k) {
    return r * 64 + ((((k >> 3) ^ (r & 7)) << 3) | (k & 7));
}
__device__ __forceinline__ uint32_t h2u(__half2 h) { return *(uint32_t*)&h; }
__device__ __forceinline__ uint4 cvt8s(float4 f0, float4 f1) {
    __half2 a = __floats2half2_rn(f0.x, f0.y), b = __floats2half2_rn(f0.z, f0.w);
    __half2 c = __floats2half2_rn(f1.x, f1.y), d = __floats2half2_rn(f1.z, f1.w);
    return make_uint4(h2u(a), h2u(b), h2u(c), h2u(d));
}
__device__ __forceinline__ void cvt8h(float4 f0, float4 f1, uint4& hi, uint4& lo) {
    __half2 h, l;
    h = __floats2half2_rn(f0.x, f0.y);
    l = __floats2half2_rn(f0.x - __half2float(__low2half(h)), f0.y - __half2float(__high2half(h)));
    hi.x = h2u(h); lo.x = h2u(l);
    h = __floats2half2_rn(f0.z, f0.w);
    l = __floats2half2_rn(f0.z - __half2float(__low2half(h)), f0.w - __half2float(__high2half(h)));
    hi.y = h2u(h); lo.y = h2u(l);
    h = __floats2half2_rn(f1.x, f1.y);
    l = __floats2half2_rn(f1.x - __half2float(__low2half(h)), f1.y - __half2float(__high2half(h)));
    hi.z = h2u(h); lo.z = h2u(l);
    h = __floats2half2_rn(f1.z, f1.w);
    l = __floats2half2_rn(f1.z - __half2float(__low2half(h)), f1.w - __half2float(__high2half(h)));
    hi.w = h2u(h); lo.w = h2u(l);
}

// GEMM smem: stage = Ahi(4096) + Alo(4096) + B(4096) halves
#define ST_STRIDE 12288
#define SM_AHI 0
#define SM_ALO 4096
#define SM_B   8192
#define SMEM_BYTES (2 * ST_STRIDE * 2)

// ---------------- fused prepass ----------------
__global__ void prep_all(const float* __restrict__ w_cpe, const float* __restrict__ w_lin,
                         const float* __restrict__ w_qkv, const float* __restrict__ w_proj,
                         const float* __restrict__ w_fc1, const float* __restrict__ w_fc2,
                         const float* __restrict__ feat)
{
    const int b = blockIdx.x, t = threadIdx.x;
    if (b < 5120) {
        const int i = b * 2048 + t * 8;
        const float* s; int o;
        if (i < OFF_LIN)       { s = w_cpe;  o = i; }
        else if (i < OFF_QKV)  { s = w_lin;  o = i - OFF_LIN; }
        else if (i < OFF_PROJ) { s = w_qkv;  o = i - OFF_QKV; }
        else if (i < OFF_FC1)  { s = w_proj; o = i - OFF_PROJ; }
        else if (i < OFF_FC2)  { s = w_fc1;  o = i - OFF_FC1; }
        else                   { s = w_fc2;  o = i - OFF_FC2; }
        float4 f0 = *(const float4*)(s + o);
        float4 f1 = *(const float4*)(s + o + 4);
        *(uint4*)(g_wh + i) = cvt8s(f0, f1);
    } else if (b < 9216) {
        const int i = (b - 5120) * 2048 + t * 8;
        float4 f0 = *(const float4*)(feat + i);
        float4 f1 = *(const float4*)(feat + i + 4);
        uint4 h, l; cvt8h(f0, f1, h, l);
        *(uint4*)(g_fhi + i) = h;
        *(uint4*)(g_flo + i) = l;
    } else if (b < 10880) {
        const int i = (b - 9216) * 256 + t;
        g_plist[i] = make_int2(-1, -1);
    } else {
        if (t < 26) { g_cnt[t] = 0; g_cursor[t] = 0; }
    }
}

__global__ void cvt_hi(const float* __restrict__ src, __half* __restrict__ hi)
{
    const int i = (blockIdx.x * blockDim.x + threadIdx.x) * 8;
    float4 f0 = *(const float4*)(src + i);
    float4 f1 = *(const float4*)(src + i + 4);
    *(uint4*)(hi + i) = cvt8s(f0, f1);
}

// ---------------- sparse CPE prepass ----------------
__global__ void prep_count(const int* __restrict__ nbr)
{
    int s = blockIdx.y, kk = (s < 13) ? s : s + 1;
    int n = blockIdx.x * blockDim.x + threadIdx.x;
    bool v = __ldg(nbr + (size_t)n * 27 + kk) >= 0;
    unsigned m = __ballot_sync(0xffffffffu, v);
    if ((threadIdx.x & 31) == 0 && m) atomicAdd(&g_cnt[s], __popc(m));
}
__global__ void prep_scan()
{
    __shared__ int sofs[27];
    if (threadIdx.x == 0) {
        int o = 0;
        for (int s = 0; s < 26; ++s) {
            sofs[s] = o; g_pofs[s] = o;
            o += ((g_cnt[s] + 127) >> 7) << 7;
        }
        sofs[26] = o; g_pofs[26] = o; g_ntiles = o >> 7;
    }
    __syncthreads();
    int nt = sofs[26] >> 7;
    for (int tile = threadIdx.x; tile < nt; tile += blockDim.x) {
        int pos = tile << 7;
        int s = 0;
        while (!(pos >= sofs[s] && pos < sofs[s + 1])) ++s;
        g_tiletap[tile] = (s < 13) ? s : s + 1;
    }
}
__global__ void prep_fill(const int* __restrict__ nbr)
{
    int s = blockIdx.y, kk = (s < 13) ? s : s + 1;
    int n = blockIdx.x * blockDim.x + threadIdx.x;
    int j = __ldg(nbr + (size_t)n * 27 + kk);
    bool v = j >= 0;
    unsigned m = __ballot_sync(0xffffffffu, v);
    int base = 0;
    if ((threadIdx.x & 31) == 0 && m) base = atomicAdd(&g_cursor[s], __popc(m));
    base = __shfl_sync(0xffffffffu, base, 0);
    if (v) {
        int pos = base + __popc(m & ((1u << (threadIdx.x & 31)) - 1));
        g_plist[g_pofs[s] + pos] = make_int2(n, j);
    }
}

// ---------------- core mma on one resident chunk ----------------
template <bool ASPLIT>
__device__ __forceinline__ void mma_chunk(const __half* sbuf, int wm, int wn, int lane,
                                          float acc[4][4][4])
{
#pragma unroll
    for (int kk16 = 0; kk16 < 2; ++kk16) {
        const int kc = kk16 * 2 + (lane >> 4);
        uint32_t ah[4][4], al[4][4], bb[2][4];
#pragma unroll
        for (int mf = 0; mf < 4; ++mf) {
            const int row = wm * 64 + mf * 16 + (lane & 15);
            const int off = sidx(row, kc * 8);
            ldmx4(ah[mf][0], ah[mf][1], ah[mf][2], ah[mf][3], s2u(sbuf + SM_AHI + off));
            if (ASPLIT)
                ldmx4(al[mf][0], al[mf][1], al[mf][2], al[mf][3], s2u(sbuf + SM_ALO + off));
        }
#pragma unroll
        for (int np = 0; np < 2; ++np) {
            const int row = wn * 32 + np * 16 + (lane & 15);
            const int off = sidx(row, kc * 8);
            ldmx4(bb[np][0], bb[np][1], bb[np][2], bb[np][3], s2u(sbuf + SM_B + off));
        }
#pragma unroll
        for (int mf = 0; mf < 4; ++mf) {
#pragma unroll
            for (int nf = 0; nf < 4; ++nf) {
                const int pr = nf >> 1, sb = nf & 1;
                mma_f16(acc[mf][nf], ah[mf], bb[pr][sb], bb[pr][sb + 2]);
                if (ASPLIT)
                    mma_f16(acc[mf][nf], al[mf], bb[pr][sb], bb[pr][sb + 2]);
            }
        }
    }
}

// ---------------- epilogue ----------------
template <bool GELU, bool RES, bool WF32, bool WHI>
__device__ __forceinline__ void epilogue(float acc[4][4][4], int bm, int bn, int Nn,
                                         int wm, int wn, int lane,
                                         const float* bias, const float* res,
                                         float* outf, __half* outhi)
{
#pragma unroll
    for (int mf = 0; mf < 4; ++mf) {
#pragma unroll
        for (int nf = 0; nf < 4; ++nf) {
            const int n0 = bn + wn * 32 + nf * 8 + 2 * (lane & 3);
            const float b0 = __ldg(bias + n0), b1 = __ldg(bias + n0 + 1);
#pragma unroll
            for (int half = 0; half < 2; ++half) {
                const int m = bm + wm * 64 + mf * 16 + (lane >> 2) + half * 8;
                float v0 = acc[mf][nf][half * 2 + 0] + b0;
                float v1 = acc[mf][nf][half * 2 + 1] + b1;
                if (GELU) {
                    v0 = 0.5f * v0 * (1.f + erff(v0 * 0.70710678118f));
                    v1 = 0.5f * v1 * (1.f + erff(v1 * 0.70710678118f));
                }
                if (RES) {
                    float2 r2 = *(const float2*)(res + (size_t)m * Nn + n0);
                    v0 += r2.x; v1 += r2.y;
                }
                if (WF32)
                    *(float2*)(outf + (size_t)m * Nn + n0) = make_float2(v0, v1);
                if (WHI)
                    *(uint32_t*)(outhi + (size_t)m * Nn + n0) = h2u(__floats2half2_rn(v0, v1));
            }
        }
    }
}

// ---------------- dense GEMM ----------------
template <bool GELU, bool RES, bool WF32, bool WHI, bool ASPLIT>
__global__ void __launch_bounds__(256)
tc_gemm(const __half* __restrict__ Ahi, const __half* __restrict__ Alo,
        const __half* __restrict__ Bh,
        const float* __restrict__ bias, const float* __restrict__ res,
        float* __restrict__ outf, __half* __restrict__ outhi,
        int Nn, int Kk)
{
    extern __shared__ __align__(16) __half smem[];
    const int t = threadIdx.x, lane = t & 31, warp = t >> 5;
    const int wm = warp >> 2, wn = warp & 3;
    const int bm = blockIdx.y * 128, bn = blockIdx.x * 128;

    float acc[4][4][4];
#pragma unroll
    for (int a = 0; a < 4; ++a)
#pragma unroll
        for (int b = 0; b < 4; ++b)
#pragma unroll
            for (int c = 0; c < 4; ++c) acc[a][b][c] = 0.f;

    const int nchunk = Kk / 32;
    const int r0 = t >> 2, c0 = t & 3;
    const int r1 = (t + 256) >> 2;
    const size_t a0 = (size_t)(bm + r0) * Kk + c0 * 8;
    const size_t a1 = (size_t)(bm + r1) * Kk + c0 * 8;
    const size_t b0 = (size_t)(bn + r0) * Kk + c0 * 8;
    const size_t b1 = (size_t)(bn + r1) * Kk + c0 * 8;

    *(uint4*)(smem + SM_AHI + sidx(r0, c0 * 8)) = *(const uint4*)(Ahi + a0);
    *(uint4*)(smem + SM_AHI + sidx(r1, c0 * 8)) = *(const uint4*)(Ahi + a1);
    if (ASPLIT) {
        *(uint4*)(smem + SM_ALO + sidx(r0, c0 * 8)) = *(const uint4*)(Alo + a0);
        *(uint4*)(smem + SM_ALO + sidx(r1, c0 * 8)) = *(const uint4*)(Alo + a1);
    }
    *(uint4*)(smem + SM_B + sidx(r0, c0 * 8)) = *(const uint4*)(Bh + b0);
    *(uint4*)(smem + SM_B + sidx(r1, c0 * 8)) = *(const uint4*)(Bh + b1);
    __syncthreads();

    for (int chunk = 0; chunk < nchunk; ++chunk) {
        const __half* cur = smem + (chunk & 1) * ST_STRIDE;
        __half* nxt = smem + ((chunk + 1) & 1) * ST_STRIDE;
        uint4 pah0, pal0, pah1, pal1, pb0, pb1;
        const bool more = (chunk + 1 < nchunk);
        if (more) {
            const int kb = (chunk + 1) * 32;
            pah0 = *(const uint4*)(Ahi + a0 + kb);
            pah1 = *(const uint4*)(Ahi + a1 + kb);
            if (ASPLIT) {
                pal0 = *(const uint4*)(Alo + a0 + kb);
                pal1 = *(const uint4*)(Alo + a1 + kb);
            }
            pb0 = *(const uint4*)(Bh + b0 + kb);
            pb1 = *(const uint4*)(Bh + b1 + kb);
        }
        mma_chunk<ASPLIT>(cur, wm, wn, lane, acc);
        __syncthreads();
        if (more) {
            *(uint4*)(nxt + SM_AHI + sidx(r0, c0 * 8)) = pah0;
            *(uint4*)(nxt + SM_AHI + sidx(r1, c0 * 8)) = pah1;
            if (ASPLIT) {
                *(uint4*)(nxt + SM_ALO + sidx(r0, c0 * 8)) = pal0;
                *(uint4*)(nxt + SM_ALO + sidx(r1, c0 * 8)) = pal1;
            }
            *(uint4*)(nxt + SM_B + sidx(r0, c0 * 8)) = pb0;
            *(uint4*)(nxt + SM_B + sidx(r1, c0 * 8)) = pb1;
        }
        __syncthreads();
    }
    epilogue<GELU, RES, WF32, WHI>(acc, bm, bn, Nn, wm, wn, lane, bias, res, outf, outhi);
}

// ---------------- sparse CPE GEMM (keeps A 2-split) ----------------
__global__ void __launch_bounds__(256)
cpe_sparse(const __half* __restrict__ fhi, const __half* __restrict__ flo,
           const __half* __restrict__ W, float* __restrict__ out)
{
    extern __shared__ __align__(16) __half smem[];
    __shared__ int sn[128];
    const int t = threadIdx.x, lane = t & 31, warp = t >> 5;
    const int wm = warp >> 2, wn = warp & 3;
    const int bn = blockIdx.x * 128;
    const int r0 = t >> 2, c0 = t & 3;
    const int r1 = (t + 256) >> 2;

    for (int tile = blockIdx.y; tile < g_ntiles; tile += gridDim.y) {
        __syncthreads();
        const int kk = g_tiletap[tile];
        const __half* Wk = W + (size_t)kk * C * C;
        const int2* pl = g_plist + (size_t)tile * 128;
        if (t < 128) sn[t] = pl[t].x;

        float acc[4][4][4];
#pragma unroll
        for (int a = 0; a < 4; ++a)
#pragma unroll
            for (int b = 0; b < 4; ++b)
#pragma unroll
                for (int c = 0; c < 4; ++c) acc[a][b][c] = 0.f;

        const int j0 = __ldg(&pl[r0].y), j1 = __ldg(&pl[r1].y);
        const size_t f0 = (size_t)(j0 < 0 ? 0 : j0) * C + c0 * 8;
        const size_t f1 = (size_t)(j1 < 0 ? 0 : j1) * C + c0 * 8;
        const uint4 zz = make_uint4(0, 0, 0, 0);

        *(uint4*)(smem + SM_AHI + sidx(r0, c0 * 8)) = (j0 >= 0) ? *(const uint4*)(fhi + f0) : zz;
        *(uint4*)(smem + SM_ALO + sidx(r0, c0 * 8)) = (j0 >= 0) ? *(const uint4*)(flo + f0) : zz;
        *(uint4*)(smem + SM_AHI + sidx(r1, c0 * 8)) = (j1 >= 0) ? *(const uint4*)(fhi + f1) : zz;
        *(uint4*)(smem + SM_ALO + sidx(r1, c0 * 8)) = (j1 >= 0) ? *(const uint4*)(flo + f1) : zz;
        *(uint4*)(smem + SM_B + sidx(r0, c0 * 8)) = *(const uint4*)(Wk + (size_t)(bn + r0) * C + c0 * 8);
        *(uint4*)(smem + SM_B + sidx(r1, c0 * 8)) = *(const uint4*)(Wk + (size_t)(bn + r1) * C + c0 * 8);
        __syncthreads();

        const int nchunk = C / 32;
        for (int chunk = 0; chunk < nchunk; ++chunk) {
            const __half* cur = smem + (chunk & 1) * ST_STRIDE;
            __half* nxt = smem + ((chunk + 1) & 1) * ST_STRIDE;
            uint4 pah0, pal0, pah1, pal1, pb0, pb1;
            const bool more = (chunk + 1 < nchunk);
            if (more) {
                const int kb = (chunk + 1) * 32;
                pah0 = (j0 >= 0) ? *(const uint4*)(fhi + f0 + kb) : zz;
                pal0 = (j0 >= 0) ? *(const uint4*)(flo + f0 + kb) : zz;
                pah1 = (j1 >= 0) ? *(const uint4*)(fhi + f1 + kb) : zz;
                pal1 = (j1 >= 0) ? *(const uint4*)(flo + f1 + kb) : zz;
                pb0 = *(const uint4*)(Wk + (size_t)(bn + r0) * C + kb + c0 * 8);
                pb1 = *(const uint4*)(Wk + (size_t)(bn + r1) * C + kb + c0 * 8);
            }
            mma_chunk<true>(cur, wm, wn, lane, acc);
            __syncthreads();
            if (more) {
                *(uint4*)(nxt + SM_AHI + sidx(r0, c0 * 8)) = pah0;
                *(uint4*)(nxt + SM_ALO + sidx(r0, c0 * 8)) = pal0;
                *(uint4*)(nxt + SM_AHI + sidx(r1, c0 * 8)) = pah1;
                *(uint4*)(nxt + SM_ALO + sidx(r1, c0 * 8)) = pal1;
                *(uint4*)(nxt + SM_B + sidx(r0, c0 * 8)) = pb0;
                *(uint4*)(nxt + SM_B + sidx(r1, c0 * 8)) = pb1;
            }
            __syncthreads();
        }
#pragma unroll
        for (int mf = 0; mf < 4; ++mf) {
#pragma unroll
            for (int half = 0; half < 2; ++half) {
                const int ml = wm * 64 + mf * 16 + (lane >> 2) + half * 8;
                const int n = sn[ml];
                if (n < 0) continue;
                float* dst = out + (size_t)n * C;
#pragma unroll
                for (int nf = 0; nf < 4; ++nf) {
                    const int n0 = bn + wn * 32 + nf * 8 + 2 * (lane & 3);
                    atomicAdd(dst + n0,     acc[mf][nf][half * 2 + 0]);
                    atomicAdd(dst + n0 + 1, acc[mf][nf][half * 2 + 1]);
                }
            }
        }
    }
}

// ---------------- LayerNorm ----------------
template <bool RES, bool WH16>
__global__ void ln_kernel(const float* __restrict__ in, const float* __restrict__ res,
                          const float* __restrict__ gam, const float* __restrict__ bet,
                          float* __restrict__ outf, __half* __restrict__ outhi)
{
    const int n = blockIdx.x;
    const int t = threadIdx.x;
    float4 v = *(const float4*)(in + (size_t)n * C + t * 4);
    float s1 = v.x + v.y + v.z + v.w;
    float s2 = v.x * v.x + v.y * v.y + v.z * v.z + v.w * v.w;
#pragma unroll
    for (int o = 16; o; o >>= 1) {
        s1 += __shfl_xor_sync(0xffffffffu, s1, o);
        s2 += __shfl_xor_sync(0xffffffffu, s2, o);
    }
    __shared__ float sh1[4], sh2[4];
    const int wid = t >> 5, lane = t & 31;
    if (lane == 0) { sh1[wid] = s1; sh2[wid] = s2; }
    __syncthreads();
    float S1 = sh1[0] + sh1[1] + sh1[2] + sh1[3];
    float S2 = sh2[0] + sh2[1] + sh2[2] + sh2[3];
    float mean = S1 * (1.f / C);
    float var = S2 * (1.f / C) - mean * mean;
    float inv = rsqrtf(var + 1e-5f);
    float4 g4 = *(const float4*)(gam + t * 4);
    float4 b4 = *(const float4*)(bet + t * 4);
    float4 o4;
    o4.x = (v.x - mean) * inv * g4.x + b4.x;
    o4.y = (v.y - mean) * inv * g4.y + b4.y;
    o4.z = (v.z - mean) * inv * g4.z + b4.z;
    o4.w = (v.w - mean) * inv * g4.w + b4.w;
    if (RES) {
        float4 r4 = *(const float4*)(res + (size_t)n * C + t * 4);
        o4.x += r4.x; o4.y += r4.y; o4.z += r4.z; o4.w += r4.w;
    }
    if (WH16) {
        __half2 h0 = __floats2half2_rn(o4.x, o4.y);
        __half2 h1 = __floats2half2_rn(o4.z, o4.w);
        *(uint2*)(outhi + (size_t)n * C + t * 4) = make_uint2(h2u(h0), h2u(h1));
    } else {
        *(float4*)(outf + (size_t)n * C + t * 4) = o4;
    }
}

// ---------------- tensor-core flash attention ----------------
#define ATT_Q 0
#define ATT_K 8192
#define ATT_V 16384
#define ATT_SMEM (24576 * 2)

__global__ void __launch_bounds__(256)
attn_kernel(const __half* __restrict__ qkvh, const int* __restrict__ order,
            __half* __restrict__ obhi)
{
    extern __shared__ __align__(16) __half asmem[];
    const int t = threadIdx.x, lane = t & 31, warp = t >> 5;
    const int qt = blockIdx.x, h = blockIdx.y, p = blockIdx.z;
    const int qbase = p * KWIN + qt * 128;
    const __half2 hsc = __floats2half2_rn(SCALE, SCALE);

    for (int u = t; u < 1024; u += 256) {
        int r = u >> 3, c = u & 7;
        int n = __ldg(order + qbase + r);
        uint4 q = *(const uint4*)(qkvh + (size_t)n * (3 * C) + h * HD + c * 8);
        __half2* qh = (__half2*)&q;
        qh[0] = __hmul2(qh[0], hsc); qh[1] = __hmul2(qh[1], hsc);
        qh[2] = __hmul2(qh[2], hsc); qh[3] = __hmul2(qh[3], hsc);
        *(uint4*)(asmem + ATT_Q + aidx(r, c * 8)) = q;
    }

    float mrow[2] = {-1e30f, -1e30f}, lrow[2] = {0.f, 0.f};
    float oacc[8][4];
#pragma unroll
    for (int j = 0; j < 8; ++j)
#pragma unroll
        for (int c = 0; c < 4; ++c) oacc[j][c] = 0.f;

    for (int kt = 0; kt < KWIN / 128; ++kt) {
        __syncthreads();
        for (int u = t; u < 1024; u += 256) {
            int r = u >> 3, c = u & 7;
            int n = __ldg(order + p * KWIN + kt * 128 + r);
            *(uint4*)(asmem + ATT_K + aidx(r, c * 8)) =
                *(const uint4*)(qkvh + (size_t)n * (3 * C) + C + h * HD + c * 8);
            *(uint4*)(asmem + ATT_V + aidx(r, c * 8)) =
                *(const uint4*)(qkvh + (size_t)n * (3 * C) + 2 * C + h * HD + c * 8);
        }
        __syncthreads();

        float s[16][4];
#pragma unroll
        for (int j = 0; j < 16; ++j)
#pragma unroll
            for (int c = 0; c < 4; ++c) s[j][c] = 0.f;
#pragma unroll
        for (int kk = 0; kk < 4; ++kk) {
            const int kc = kk * 2 + (lane >> 4);
            uint32_t a[4];
            {
                int row = warp * 16 + (lane & 15);
                ldmx4(a[0], a[1], a[2], a[3], s2u(asmem + ATT_Q + aidx(row, kc * 8)));
            }
#pragma unroll
            for (int np = 0; np < 8; ++np) {
                uint32_t b[4];
                int row = np * 16 + (lane & 15);
                ldmx4(b[0], b[1], b[2], b[3], s2u(asmem + ATT_K + aidx(row, kc * 8)));
                mma_f16(s[np * 2 + 0], a, b[0], b[2]);
                mma_f16(s[np * 2 + 1], a, b[1], b[3]);
            }
        }

        uint32_t ph[16][2];
#pragma unroll
        for (int half = 0; half < 2; ++half) {
            float mx = mrow[half];
#pragma unroll
            for (int j = 0; j < 16; ++j)
                mx = fmaxf(mx, fmaxf(s[j][half * 2], s[j][half * 2 + 1]));
            mx = fmaxf(mx, __shfl_xor_sync(0xffffffffu, mx, 1));
            mx = fmaxf(mx, __shfl_xor_sync(0xffffffffu, mx, 2));
            const float alpha = __expf(mrow[half] - mx);
            float sum = 0.f;
#pragma unroll
            for (int j = 0; j < 16; ++j) {
                __half2 e = h2exp2(__floats2half2_rn(
                    (s[j][half * 2] - mx) * 1.44269504f,
                    (s[j][half * 2 + 1] - mx) * 1.44269504f));
                ph[j][half] = h2u(e);
                float2 f = __half22float2(e);
                sum += f.x + f.y;
            }
            sum += __shfl_xor_sync(0xffffffffu, sum, 1);
            sum += __shfl_xor_sync(0xffffffffu, sum, 2);
            lrow[half] = lrow[half] * alpha + sum;
            mrow[half] = mx;
#pragma unroll
            for (int j = 0; j < 8; ++j) {
                oacc[j][half * 2] *= alpha;
                oacc[j][half * 2 + 1] *= alpha;
            }
        }

#pragma unroll
        for (int kc = 0; kc < 8; ++kc) {
            uint32_t pa[4] = { ph[kc * 2][0], ph[kc * 2][1], ph[kc * 2 + 1][0], ph[kc * 2 + 1][1] };
#pragma unroll
            for (int dp = 0; dp < 4; ++dp) {
                uint32_t b[4];
                int row = kc * 16 + ((lane >> 3) & 1) * 8 + (lane & 7);
                int col = dp * 16 + (lane >> 4) * 8;
                ldmx4t(b[0], b[1], b[2], b[3], s2u(asmem + ATT_V + aidx(row, col)));
                mma_f16(oacc[dp * 2 + 0], pa, b[0], b[1]);
                mma_f16(oacc[dp * 2 + 1], pa, b[2], b[3]);
            }
        }
    }

#pragma unroll
    for (int half = 0; half < 2; ++half) {
        const float inv = 1.f / lrow[half];
        const int r = warp * 16 + (lane >> 2) + half * 8;
        const int n = __ldg(order + qbase + r);
        __half* dh = obhi + (size_t)n * C + h * HD;
#pragma unroll
        for (int j = 0; j < 8; ++j) {
            const int d0 = j * 8 + 2 * (lane & 3);
            *(uint32_t*)(dh + d0) = h2u(__floats2half2_rn(oacc[j][half * 2] * inv,
                                                          oacc[j][half * 2 + 1] * inv));
        }
    }
}

// ---------------- launch ----------------
extern "C" void kernel_launch(void* const* d_in, const int* in_sizes, int n_in,
                              void* d_out, int out_size)
{
    const float* feat      = (const float*)d_in[0];
    const int*   nbr       = (const int*)d_in[1];
    const int*   order     = (const int*)d_in[2];
    const float* cpe_w     = (const float*)d_in[3];
    const float* cpe_b     = (const float*)d_in[4];
    const float* cpe_lin_w = (const float*)d_in[5];
    const float* cpe_lin_b = (const float*)d_in[6];
    const float* cpe_ln_g  = (const float*)d_in[7];
    const float* cpe_ln_b  = (const float*)d_in[8];
    const float* ln1_g     = (const float*)d_in[9];
    const float* ln1_b     = (const float*)d_in[10];
    const float* qkv_w     = (const float*)d_in[11];
    const float* qkv_b     = (const float*)d_in[12];
    const float* proj_w    = (const float*)d_in[13];
    const float* proj_b    = (const float*)d_in[14];
    const float* ln2_g     = (const float*)d_in[15];
    const float* ln2_b     = (const float*)d_in[16];
    const float* fc1_w     = (const float*)d_in[17];
    const float* fc1_b     = (const float*)d_in[18];
    const float* fc2_w     = (const float*)d_in[19];
    const float* fc2_b     = (const float*)d_in[20];
    float* out = (float*)d_out;

    float *tmp1, *tmp2, *feat1;
    __half *wh, *fhi, *flo, *t1hi, *xhi, *qkvh, *obhi, *yhi;
    cudaGetSymbolAddress((void**)&tmp1,  g_tmp1);
    cudaGetSymbolAddress((void**)&tmp2,  g_tmp2);
    cudaGetSymbolAddress((void**)&feat1, g_feat1);
    cudaGetSymbolAddress((void**)&wh,    g_wh);
    cudaGetSymbolAddress((void**)&fhi,   g_fhi);
    cudaGetSymbolAddress((void**)&flo,   g_flo);
    cudaGetSymbolAddress((void**)&t1hi,  g_t1hi);
    cudaGetSymbolAddress((void**)&xhi,   g_xhi);
    cudaGetSymbolAddress((void**)&qkvh,  g_qkvh);
    cudaGetSymbolAddress((void**)&obhi,  g_obhi);
    cudaGetSymbolAddress((void**)&yhi,   g_yhi);

    cudaFuncSetAttribute(tc_gemm<false,false,true,false,true>,   cudaFuncAttributeMaxDynamicSharedMemorySize, SMEM_BYTES);
    cudaFuncSetAttribute(tc_gemm<false,false,true,false,false>,  cudaFuncAttributeMaxDynamicSharedMemorySize, SMEM_BYTES);
    cudaFuncSetAttribute(tc_gemm<false,false,false,true,false>,  cudaFuncAttributeMaxDynamicSharedMemorySize, SMEM_BYTES);
    cudaFuncSetAttribute(tc_gemm<false,true,true,false,false>,   cudaFuncAttributeMaxDynamicSharedMemorySize, SMEM_BYTES);
    cudaFuncSetAttribute(tc_gemm<true,false,false,true,false>,   cudaFuncAttributeMaxDynamicSharedMemorySize, SMEM_BYTES);
    cudaFuncSetAttribute(cpe_sparse,  cudaFuncAttributeMaxDynamicSharedMemorySize, SMEM_BYTES);
    cudaFuncSetAttribute(attn_kernel, cudaFuncAttributeMaxDynamicSharedMemorySize, ATT_SMEM);

    // 1) fused prepass
    prep_all<<<10881, 256>>>(cpe_w, cpe_lin_w, qkv_w, proj_w, fc1_w, fc2_w, feat);
    // 2) sparse CPE prepass
    prep_count<<<dim3(NPTS / 256, 26), 256>>>(nbr);
    prep_scan<<<1, 128>>>();
    prep_fill<<<dim3(NPTS / 256, 26), 256>>>(nbr);

    const int MB = NPTS / 128;
    // 3) CPE center (split A) + sparse taps (split A)
    tc_gemm<false,false,true,false,true><<<dim3(C/128, MB), 256, SMEM_BYTES>>>(
        fhi, flo, wh + OFF_CPE + (size_t)13*C*C, cpe_b, nullptr, tmp1, nullptr, C, C);
    cpe_sparse<<<dim3(C/128, 128), 256, SMEM_BYTES>>>(fhi, flo, wh + OFF_CPE, tmp1);
    // 4) tmp1 -> fp16
    cvt_hi<<<NPTS * C / 2048, 256>>>(tmp1, t1hi);
    // 5) cpe_lin (single A)
    tc_gemm<false,false,true,false,false><<<dim3(C/128, MB), 256, SMEM_BYTES>>>(
        t1hi, nullptr, wh + OFF_LIN, cpe_lin_b, nullptr, tmp2, nullptr, C, C);
    // 6) feat1 = feat + LN(tmp2)
    ln_kernel<true,false><<<NPTS, 128>>>(tmp2, feat, cpe_ln_g, cpe_ln_b, feat1, nullptr);
    // 7) x = LN(feat1) -> fp16
    ln_kernel<false,true><<<NPTS, 128>>>(feat1, nullptr, ln1_g, ln1_b, nullptr, xhi);
    // 8) qkv (single A)
    tc_gemm<false,false,false,true,false><<<dim3(3*C/128, MB), 256, SMEM_BYTES>>>(
        xhi, nullptr, wh + OFF_QKV, qkv_b, nullptr, nullptr, qkvh, 3*C, C);
    // 9) attention
    attn_kernel<<<dim3(KWIN/128, H, P), 256, ATT_SMEM>>>(qkvh, order, obhi);
    // 10) feat2 = feat1 + proj(ob)
    tc_gemm<false,true,true,false,false><<<dim3(C/128, MB), 256, SMEM_BYTES>>>(
        obhi, nullptr, wh + OFF_PROJ, proj_b, feat1, tmp1, nullptr, C, C);
    // 11) x = LN(feat2) -> fp16
    ln_kernel<false,true><<<NPTS, 128>>>(tmp1, nullptr, ln2_g, ln2_b, nullptr, xhi);
    // 12) y = gelu(fc1(x)) -> fp16
    tc_gemm<true,false,false,true,false><<<dim3(4*C/128, MB), 256, SMEM_BYTES>>>(
        xhi, nullptr, wh + OFF_FC1, fc1_b, nullptr, nullptr, yhi, 4*C, C);
    // 13) out = feat2 + fc2(y)
    tc_gemm<false,true,true,false,false><<<dim3(C/128, MB), 256, SMEM_BYTES>>>(
        yhi, nullptr, wh + OFF_FC2, fc2_b, tmp1, out, nullptr, C, 4*C);
}

// round 7
// speedup vs baseline: 1.6314x; 1.1594x over previous
#include <cuda_runtime.h>
#include <cuda_fp16.h>
#include <math.h>
#include <stdint.h>

#define NPTS 16384
#define C 512
#define H 8
#define HD 64
#define KWIN 1024
#define P (NPTS / KWIN)
#define SCALE 0.125f
#define MAX_TILES 3328
#define MAX_TAPS 26

// ---------------- scratch ----------------
__device__ float g_tmp1[NPTS * C];
__device__ float g_tmp2[NPTS * C];
__device__ float g_feat1[NPTS * C];

__device__ __half g_fhi[NPTS * C];
__device__ __half g_t1hi[NPTS * C];
__device__ __half g_xhi[NPTS * C];
__device__ __half g_qkvh[NPTS * 3 * C];
__device__ __half g_obhi[NPTS * C];
__device__ __half g_yhi[NPTS * 4 * C];
__device__ __half g_stage[(size_t)MAX_TILES * 128 * C];   // sparse tap staging

#define WPOOL (27*C*C + C*C + 3*C*C + C*C + 4*C*C + 4*C*C)
__device__ __half g_wh[WPOOL];

#define OFF_CPE   0
#define OFF_LIN   (27*C*C)
#define OFF_QKV   (OFF_LIN + C*C)
#define OFF_PROJ  (OFF_QKV + 3*C*C)
#define OFF_FC1   (OFF_PROJ + C*C)
#define OFF_FC2   (OFF_FC1 + 4*C*C)

// sparse CPE bookkeeping
__device__ int g_cnt[26];
__device__ int g_cursor[26];
__device__ int g_pofs[27];
__device__ int g_ntiles;
__device__ int g_tiletap[MAX_TILES];
__device__ int2 g_plist[MAX_TILES * 128];
__device__ int g_pcnt[NPTS];
__device__ int g_prows[NPTS * MAX_TAPS];

// ---------------- helpers ----------------
__device__ __forceinline__ uint32_t s2u(const void* p) {
    return (uint32_t)__cvta_generic_to_shared(p);
}
__device__ __forceinline__ void ldmx4(uint32_t& r0, uint32_t& r1, uint32_t& r2, uint32_t& r3,
                                      uint32_t addr) {
    asm volatile("ldmatrix.sync.aligned.m8n8.x4.shared.b16 {%0,%1,%2,%3}, [%4];"
                 : "=r"(r0), "=r"(r1), "=r"(r2), "=r"(r3) : "r"(addr));
}
__device__ __forceinline__ void ldmx4t(uint32_t& r0, uint32_t& r1, uint32_t& r2, uint32_t& r3,
                                       uint32_t addr) {
    asm volatile("ldmatrix.sync.aligned.m8n8.x4.trans.shared.b16 {%0,%1,%2,%3}, [%4];"
                 : "=r"(r0), "=r"(r1), "=r"(r2), "=r"(r3) : "r"(addr));
}
__device__ __forceinline__ void mma_f16(float* d, const uint32_t* a, uint32_t b0, uint32_t b1) {
    asm volatile("mma.sync.aligned.m16n8k16.row.col.f32.f16.f16.f32 "
                 "{%0,%1,%2,%3},{%4,%5,%6,%7},{%8,%9},{%0,%1,%2,%3};"
                 : "+f"(d[0]), "+f"(d[1]), "+f"(d[2]), "+f"(d[3])
                 : "r"(a[0]), "r"(a[1]), "r"(a[2]), "r"(a[3]), "r"(b0), "r"(b1));
}
__device__ __forceinline__ int sidx(int r, int k) {
    return r * 32 + ((((k >> 3) ^ ((r >> 1) & 3)) << 3) | (k & 7));
}
__device__ __forceinline__ int aidx(int r, int k) {
    return r * 64 + ((((k >> 3) ^ (r & 7)) << 3) | (k & 7));
}
__device__ __forceinline__ uint32_t h2u(__half2 h) { return *(uint32_t*)&h; }
__device__ __forceinline__ uint4 cvt8s(float4 f0, float4 f1) {
    __half2 a = __floats2half2_rn(f0.x, f0.y), b = __floats2half2_rn(f0.z, f0.w);
    __half2 c = __floats2half2_rn(f1.x, f1.y), d = __floats2half2_rn(f1.z, f1.w);
    return make_uint4(h2u(a), h2u(b), h2u(c), h2u(d));
}

// GEMM smem: stage = A(4096) + B(4096) halves
#define ST_STRIDE 8192
#define SM_A 0
#define SM_B 4096
#define SMEM_BYTES (2 * ST_STRIDE * 2)

// ---------------- fused prepass ----------------
__global__ void prep_all(const float* __restrict__ w_cpe, const float* __restrict__ w_lin,
                         const float* __restrict__ w_qkv, const float* __restrict__ w_proj,
                         const float* __restrict__ w_fc1, const float* __restrict__ w_fc2,
                         const float* __restrict__ feat)
{
    const int b = blockIdx.x, t = threadIdx.x;
    if (b < 5120) {
        const int i = b * 2048 + t * 8;
        const float* s; int o;
        if (i < OFF_LIN)       { s = w_cpe;  o = i; }
        else if (i < OFF_QKV)  { s = w_lin;  o = i - OFF_LIN; }
        else if (i < OFF_PROJ) { s = w_qkv;  o = i - OFF_QKV; }
        else if (i < OFF_FC1)  { s = w_proj; o = i - OFF_PROJ; }
        else if (i < OFF_FC2)  { s = w_fc1;  o = i - OFF_FC1; }
        else                   { s = w_fc2;  o = i - OFF_FC2; }
        float4 f0 = *(const float4*)(s + o);
        float4 f1 = *(const float4*)(s + o + 4);
        *(uint4*)(g_wh + i) = cvt8s(f0, f1);
    } else if (b < 9216) {
        const int i = (b - 5120) * 2048 + t * 8;
        float4 f0 = *(const float4*)(feat + i);
        float4 f1 = *(const float4*)(feat + i + 4);
        *(uint4*)(g_fhi + i) = cvt8s(f0, f1);
    } else if (b < 10880) {
        const int i = (b - 9216) * 256 + t;
        g_plist[i] = make_int2(-1, -1);
    } else if (b < 10944) {
        g_pcnt[(b - 10880) * 256 + t] = 0;
    } else {
        if (t < 26) { g_cnt[t] = 0; g_cursor[t] = 0; }
    }
}

// ---------------- sparse CPE prepass ----------------
__global__ void prep_count(const int* __restrict__ nbr)
{
    int s = blockIdx.y, kk = (s < 13) ? s : s + 1;
    int n = blockIdx.x * blockDim.x + threadIdx.x;
    bool v = __ldg(nbr + (size_t)n * 27 + kk) >= 0;
    unsigned m = __ballot_sync(0xffffffffu, v);
    if ((threadIdx.x & 31) == 0 && m) atomicAdd(&g_cnt[s], __popc(m));
}
__global__ void prep_scan()
{
    __shared__ int sofs[27];
    if (threadIdx.x == 0) {
        int o = 0;
        for (int s = 0; s < 26; ++s) {
            sofs[s] = o; g_pofs[s] = o;
            o += ((g_cnt[s] + 127) >> 7) << 7;
        }
        sofs[26] = o; g_pofs[26] = o; g_ntiles = o >> 7;
    }
    __syncthreads();
    int nt = sofs[26] >> 7;
    for (int tile = threadIdx.x; tile < nt; tile += blockDim.x) {
        int pos = tile << 7;
        int s = 0;
        while (!(pos >= sofs[s] && pos < sofs[s + 1])) ++s;
        g_tiletap[tile] = (s < 13) ? s : s + 1;
    }
}
__global__ void prep_fill(const int* __restrict__ nbr)
{
    int s = blockIdx.y, kk = (s < 13) ? s : s + 1;
    int n = blockIdx.x * blockDim.x + threadIdx.x;
    int j = __ldg(nbr + (size_t)n * 27 + kk);
    bool v = j >= 0;
    unsigned m = __ballot_sync(0xffffffffu, v);
    int base = 0;
    if ((threadIdx.x & 31) == 0 && m) base = atomicAdd(&g_cursor[s], __popc(m));
    base = __shfl_sync(0xffffffffu, base, 0);
    if (v) {
        int pos = base + __popc(m & ((1u << (threadIdx.x & 31)) - 1));
        int srow = g_pofs[s] + pos;
        g_plist[srow] = make_int2(n, j);
        int slot = atomicAdd(&g_pcnt[n], 1);
        g_prows[n * MAX_TAPS + slot] = srow;
    }
}

// ---------------- core mma on one resident chunk (single fp16) ----------------
__device__ __forceinline__ void mma_chunk(const __half* sbuf, int wm, int wn, int lane,
                                          float acc[4][4][4])
{
#pragma unroll
    for (int kk16 = 0; kk16 < 2; ++kk16) {
        const int kc = kk16 * 2 + (lane >> 4);
        uint32_t aa[4][4], bb[2][4];
#pragma unroll
        for (int mf = 0; mf < 4; ++mf) {
            const int row = wm * 64 + mf * 16 + (lane & 15);
            ldmx4(aa[mf][0], aa[mf][1], aa[mf][2], aa[mf][3],
                  s2u(sbuf + SM_A + sidx(row, kc * 8)));
        }
#pragma unroll
        for (int np = 0; np < 2; ++np) {
            const int row = wn * 32 + np * 16 + (lane & 15);
            ldmx4(bb[np][0], bb[np][1], bb[np][2], bb[np][3],
                  s2u(sbuf + SM_B + sidx(row, kc * 8)));
        }
#pragma unroll
        for (int mf = 0; mf < 4; ++mf) {
#pragma unroll
            for (int nf = 0; nf < 4; ++nf) {
                const int pr = nf >> 1, sb = nf & 1;
                mma_f16(acc[mf][nf], aa[mf], bb[pr][sb], bb[pr][sb + 2]);
            }
        }
    }
}

// ---------------- epilogue ----------------
template <bool GELU, bool RES, bool WF32, bool WHI>
__device__ __forceinline__ void epilogue(float acc[4][4][4], int bm, int bn, int Nn,
                                         int wm, int wn, int lane,
                                         const float* bias, const float* res,
                                         float* outf, __half* outhi)
{
#pragma unroll
    for (int mf = 0; mf < 4; ++mf) {
#pragma unroll
        for (int nf = 0; nf < 4; ++nf) {
            const int n0 = bn + wn * 32 + nf * 8 + 2 * (lane & 3);
            const float b0 = __ldg(bias + n0), b1 = __ldg(bias + n0 + 1);
#pragma unroll
            for (int half = 0; half < 2; ++half) {
                const int m = bm + wm * 64 + mf * 16 + (lane >> 2) + half * 8;
                float v0 = acc[mf][nf][half * 2 + 0] + b0;
                float v1 = acc[mf][nf][half * 2 + 1] + b1;
                if (GELU) {
                    v0 = 0.5f * v0 * (1.f + erff(v0 * 0.70710678118f));
                    v1 = 0.5f * v1 * (1.f + erff(v1 * 0.70710678118f));
                }
                if (RES) {
                    float2 r2 = *(const float2*)(res + (size_t)m * Nn + n0);
                    v0 += r2.x; v1 += r2.y;
                }
                if (WF32)
                    *(float2*)(outf + (size_t)m * Nn + n0) = make_float2(v0, v1);
                if (WHI)
                    *(uint32_t*)(outhi + (size_t)m * Nn + n0) = h2u(__floats2half2_rn(v0, v1));
            }
        }
    }
}

// ---------------- dense GEMM ----------------
template <bool GELU, bool RES, bool WF32, bool WHI>
__global__ void __launch_bounds__(256)
tc_gemm(const __half* __restrict__ Ah, const __half* __restrict__ Bh,
        const float* __restrict__ bias, const float* __restrict__ res,
        float* __restrict__ outf, __half* __restrict__ outhi,
        int Nn, int Kk)
{
    extern __shared__ __align__(16) __half smem[];
    const int t = threadIdx.x, lane = t & 31, warp = t >> 5;
    const int wm = warp >> 2, wn = warp & 3;
    const int bm = blockIdx.y * 128, bn = blockIdx.x * 128;

    float acc[4][4][4];
#pragma unroll
    for (int a = 0; a < 4; ++a)
#pragma unroll
        for (int b = 0; b < 4; ++b)
#pragma unroll
            for (int c = 0; c < 4; ++c) acc[a][b][c] = 0.f;

    const int nchunk = Kk / 32;
    const int r0 = t >> 2, c0 = t & 3;
    const int r1 = (t + 256) >> 2;
    const size_t a0 = (size_t)(bm + r0) * Kk + c0 * 8;
    const size_t a1 = (size_t)(bm + r1) * Kk + c0 * 8;
    const size_t b0 = (size_t)(bn + r0) * Kk + c0 * 8;
    const size_t b1 = (size_t)(bn + r1) * Kk + c0 * 8;

    *(uint4*)(smem + SM_A + sidx(r0, c0 * 8)) = *(const uint4*)(Ah + a0);
    *(uint4*)(smem + SM_A + sidx(r1, c0 * 8)) = *(const uint4*)(Ah + a1);
    *(uint4*)(smem + SM_B + sidx(r0, c0 * 8)) = *(const uint4*)(Bh + b0);
    *(uint4*)(smem + SM_B + sidx(r1, c0 * 8)) = *(const uint4*)(Bh + b1);
    __syncthreads();

    for (int chunk = 0; chunk < nchunk; ++chunk) {
        const __half* cur = smem + (chunk & 1) * ST_STRIDE;
        __half* nxt = smem + ((chunk + 1) & 1) * ST_STRIDE;
        uint4 pa0, pa1, pb0, pb1;
        const bool more = (chunk + 1 < nchunk);
        if (more) {
            const int kb = (chunk + 1) * 32;
            pa0 = *(const uint4*)(Ah + a0 + kb);
            pa1 = *(const uint4*)(Ah + a1 + kb);
            pb0 = *(const uint4*)(Bh + b0 + kb);
            pb1 = *(const uint4*)(Bh + b1 + kb);
        }
        mma_chunk(cur, wm, wn, lane, acc);
        __syncthreads();
        if (more) {
            *(uint4*)(nxt + SM_A + sidx(r0, c0 * 8)) = pa0;
            *(uint4*)(nxt + SM_A + sidx(r1, c0 * 8)) = pa1;
            *(uint4*)(nxt + SM_B + sidx(r0, c0 * 8)) = pb0;
            *(uint4*)(nxt + SM_B + sidx(r1, c0 * 8)) = pb1;
        }
        __syncthreads();
    }
    epilogue<GELU, RES, WF32, WHI>(acc, bm, bn, Nn, wm, wn, lane, bias, res, outf, outhi);
}

// ---------------- sparse CPE GEMM: stage fp16 output per (tile,row) ----------------
__global__ void __launch_bounds__(256)
cpe_sparse(const __half* __restrict__ fhi, const __half* __restrict__ W,
           __half* __restrict__ stage)
{
    extern __shared__ __align__(16) __half smem[];
    const int t = threadIdx.x, lane = t & 31, warp = t >> 5;
    const int wm = warp >> 2, wn = warp & 3;
    const int bn = blockIdx.x * 128;
    const int r0 = t >> 2, c0 = t & 3;
    const int r1 = (t + 256) >> 2;

    for (int tile = blockIdx.y; tile < g_ntiles; tile += gridDim.y) {
        __syncthreads();
        const int kk = g_tiletap[tile];
        const __half* Wk = W + (size_t)kk * C * C;
        const int2* pl = g_plist + (size_t)tile * 128;

        float acc[4][4][4];
#pragma unroll
        for (int a = 0; a < 4; ++a)
#pragma unroll
            for (int b = 0; b < 4; ++b)
#pragma unroll
                for (int c = 0; c < 4; ++c) acc[a][b][c] = 0.f;

        const int j0 = __ldg(&pl[r0].y), j1 = __ldg(&pl[r1].y);
        const size_t f0 = (size_t)(j0 < 0 ? 0 : j0) * C + c0 * 8;
        const size_t f1 = (size_t)(j1 < 0 ? 0 : j1) * C + c0 * 8;
        const uint4 zz = make_uint4(0, 0, 0, 0);

        *(uint4*)(smem + SM_A + sidx(r0, c0 * 8)) = (j0 >= 0) ? *(const uint4*)(fhi + f0) : zz;
        *(uint4*)(smem + SM_A + sidx(r1, c0 * 8)) = (j1 >= 0) ? *(const uint4*)(fhi + f1) : zz;
        *(uint4*)(smem + SM_B + sidx(r0, c0 * 8)) = *(const uint4*)(Wk + (size_t)(bn + r0) * C + c0 * 8);
        *(uint4*)(smem + SM_B + sidx(r1, c0 * 8)) = *(const uint4*)(Wk + (size_t)(bn + r1) * C + c0 * 8);
        __syncthreads();

        const int nchunk = C / 32;
        for (int chunk = 0; chunk < nchunk; ++chunk) {
            const __half* cur = smem + (chunk & 1) * ST_STRIDE;
            __half* nxt = smem + ((chunk + 1) & 1) * ST_STRIDE;
            uint4 pa0, pa1, pb0, pb1;
            const bool more = (chunk + 1 < nchunk);
            if (more) {
                const int kb = (chunk + 1) * 32;
                pa0 = (j0 >= 0) ? *(const uint4*)(fhi + f0 + kb) : zz;
                pa1 = (j1 >= 0) ? *(const uint4*)(fhi + f1 + kb) : zz;
                pb0 = *(const uint4*)(Wk + (size_t)(bn + r0) * C + kb + c0 * 8);
                pb1 = *(const uint4*)(Wk + (size_t)(bn + r1) * C + kb + c0 * 8);
            }
            mma_chunk(cur, wm, wn, lane, acc);
            __syncthreads();
            if (more) {
                *(uint4*)(nxt + SM_A + sidx(r0, c0 * 8)) = pa0;
                *(uint4*)(nxt + SM_A + sidx(r1, c0 * 8)) = pa1;
                *(uint4*)(nxt + SM_B + sidx(r0, c0 * 8)) = pb0;
                *(uint4*)(nxt + SM_B + sidx(r1, c0 * 8)) = pb1;
            }
            __syncthreads();
        }
        // store fp16 staging (no atomics; padded rows never read)
#pragma unroll
        for (int mf = 0; mf < 4; ++mf) {
#pragma unroll
            for (int half = 0; half < 2; ++half) {
                const int ml = wm * 64 + mf * 16 + (lane >> 2) + half * 8;
                __half* dst = stage + ((size_t)tile * 128 + ml) * C;
#pragma unroll
                for (int nf = 0; nf < 4; ++nf) {
                    const int n0 = bn + wn * 32 + nf * 8 + 2 * (lane & 3);
                    *(uint32_t*)(dst + n0) =
                        h2u(__floats2half2_rn(acc[mf][nf][half * 2 + 0],
                                              acc[mf][nf][half * 2 + 1]));
                }
            }
        }
    }
}

// ---------------- gather-reduce: t1hi = fp16(center(tmp1) + sum(staged taps)) ----------------
__global__ void cpe_reduce(const float* __restrict__ tmp1, const __half* __restrict__ stage,
                           __half* __restrict__ t1hi)
{
    const int n = blockIdx.x, t = threadIdx.x;
    const int c4 = t * 4;
    float4 v = *(const float4*)(tmp1 + (size_t)n * C + c4);
    const int cnt = g_pcnt[n];
    for (int i = 0; i < cnt; ++i) {
        const int srow = g_prows[n * MAX_TAPS + i];
        uint2 d = *(const uint2*)(stage + (size_t)srow * C + c4);
        float2 f0 = __half22float2(*(__half2*)&d.x);
        float2 f1 = __half22float2(*(__half2*)&d.y);
        v.x += f0.x; v.y += f0.y; v.z += f1.x; v.w += f1.y;
    }
    __half2 h0 = __floats2half2_rn(v.x, v.y);
    __half2 h1 = __floats2half2_rn(v.z, v.w);
    *(uint2*)(t1hi + (size_t)n * C + c4) = make_uint2(h2u(h0), h2u(h1));
}

// ---------------- LayerNorm ----------------
template <bool RES, bool WH16>
__global__ void ln_kernel(const float* __restrict__ in, const float* __restrict__ res,
                          const float* __restrict__ gam, const float* __restrict__ bet,
                          float* __restrict__ outf, __half* __restrict__ outhi)
{
    const int n = blockIdx.x;
    const int t = threadIdx.x;
    float4 v = *(const float4*)(in + (size_t)n * C + t * 4);
    float s1 = v.x + v.y + v.z + v.w;
    float s2 = v.x * v.x + v.y * v.y + v.z * v.z + v.w * v.w;
#pragma unroll
    for (int o = 16; o; o >>= 1) {
        s1 += __shfl_xor_sync(0xffffffffu, s1, o);
        s2 += __shfl_xor_sync(0xffffffffu, s2, o);
    }
    __shared__ float sh1[4], sh2[4];
    const int wid = t >> 5, lane = t & 31;
    if (lane == 0) { sh1[wid] = s1; sh2[wid] = s2; }
    __syncthreads();
    float S1 = sh1[0] + sh1[1] + sh1[2] + sh1[3];
    float S2 = sh2[0] + sh2[1] + sh2[2] + sh2[3];
    float mean = S1 * (1.f / C);
    float var = S2 * (1.f / C) - mean * mean;
    float inv = rsqrtf(var + 1e-5f);
    float4 g4 = *(const float4*)(gam + t * 4);
    float4 b4 = *(const float4*)(bet + t * 4);
    float4 o4;
    o4.x = (v.x - mean) * inv * g4.x + b4.x;
    o4.y = (v.y - mean) * inv * g4.y + b4.y;
    o4.z = (v.z - mean) * inv * g4.z + b4.z;
    o4.w = (v.w - mean) * inv * g4.w + b4.w;
    if (RES) {
        float4 r4 = *(const float4*)(res + (size_t)n * C + t * 4);
        o4.x += r4.x; o4.y += r4.y; o4.z += r4.z; o4.w += r4.w;
    }
    if (WH16) {
        __half2 h0 = __floats2half2_rn(o4.x, o4.y);
        __half2 h1 = __floats2half2_rn(o4.z, o4.w);
        *(uint2*)(outhi + (size_t)n * C + t * 4) = make_uint2(h2u(h0), h2u(h1));
    } else {
        *(float4*)(outf + (size_t)n * C + t * 4) = o4;
    }
}

// ---------------- tensor-core flash attention ----------------
#define ATT_Q 0
#define ATT_K 8192
#define ATT_V 16384
#define ATT_SMEM (24576 * 2)

__global__ void __launch_bounds__(256)
attn_kernel(const __half* __restrict__ qkvh, const int* __restrict__ order,
            __half* __restrict__ obhi)
{
    extern __shared__ __align__(16) __half asmem[];
    const int t = threadIdx.x, lane = t & 31, warp = t >> 5;
    const int qt = blockIdx.x, h = blockIdx.y, p = blockIdx.z;
    const int qbase = p * KWIN + qt * 128;
    const __half2 hsc = __floats2half2_rn(SCALE, SCALE);

    for (int u = t; u < 1024; u += 256) {
        int r = u >> 3, c = u & 7;
        int n = __ldg(order + qbase + r);
        uint4 q = *(const uint4*)(qkvh + (size_t)n * (3 * C) + h * HD + c * 8);
        __half2* qh = (__half2*)&q;
        qh[0] = __hmul2(qh[0], hsc); qh[1] = __hmul2(qh[1], hsc);
        qh[2] = __hmul2(qh[2], hsc); qh[3] = __hmul2(qh[3], hsc);
        *(uint4*)(asmem + ATT_Q + aidx(r, c * 8)) = q;
    }

    float mrow[2] = {-1e30f, -1e30f}, lrow[2] = {0.f, 0.f};
    float oacc[8][4];
#pragma unroll
    for (int j = 0; j < 8; ++j)
#pragma unroll
        for (int c = 0; c < 4; ++c) oacc[j][c] = 0.f;

    for (int kt = 0; kt < KWIN / 128; ++kt) {
        __syncthreads();
        for (int u = t; u < 1024; u += 256) {
            int r = u >> 3, c = u & 7;
            int n = __ldg(order + p * KWIN + kt * 128 + r);
            *(uint4*)(asmem + ATT_K + aidx(r, c * 8)) =
                *(const uint4*)(qkvh + (size_t)n * (3 * C) + C + h * HD + c * 8);
            *(uint4*)(asmem + ATT_V + aidx(r, c * 8)) =
                *(const uint4*)(qkvh + (size_t)n * (3 * C) + 2 * C + h * HD + c * 8);
        }
        __syncthreads();

        float s[16][4];
#pragma unroll
        for (int j = 0; j < 16; ++j)
#pragma unroll
            for (int c = 0; c < 4; ++c) s[j][c] = 0.f;
#pragma unroll
        for (int kk = 0; kk < 4; ++kk) {
            const int kc = kk * 2 + (lane >> 4);
            uint32_t a[4];
            {
                int row = warp * 16 + (lane & 15);
                ldmx4(a[0], a[1], a[2], a[3], s2u(asmem + ATT_Q + aidx(row, kc * 8)));
            }
#pragma unroll
            for (int np = 0; np < 8; ++np) {
                uint32_t b[4];
                int row = np * 16 + (lane & 15);
                ldmx4(b[0], b[1], b[2], b[3], s2u(asmem + ATT_K + aidx(row, kc * 8)));
                mma_f16(s[np * 2 + 0], a, b[0], b[2]);
                mma_f16(s[np * 2 + 1], a, b[1], b[3]);
            }
        }

        uint32_t ph[16][2];
#pragma unroll
        for (int half = 0; half < 2; ++half) {
            float mx = mrow[half];
#pragma unroll
            for (int j = 0; j < 16; ++j)
                mx = fmaxf(mx, fmaxf(s[j][half * 2], s[j][half * 2 + 1]));
            mx = fmaxf(mx, __shfl_xor_sync(0xffffffffu, mx, 1));
            mx = fmaxf(mx, __shfl_xor_sync(0xffffffffu, mx, 2));
            const float alpha = __expf(mrow[half] - mx);
            float sum = 0.f;
#pragma unroll
            for (int j = 0; j < 16; ++j) {
                __half2 e = h2exp2(__floats2half2_rn(
                    (s[j][half * 2] - mx) * 1.44269504f,
                    (s[j][half * 2 + 1] - mx) * 1.44269504f));
                ph[j][half] = h2u(e);
                float2 f = __half22float2(e);
                sum += f.x + f.y;
            }
            sum += __shfl_xor_sync(0xffffffffu, sum, 1);
            sum += __shfl_xor_sync(0xffffffffu, sum, 2);
            lrow[half] = lrow[half] * alpha + sum;
            mrow[half] = mx;
#pragma unroll
            for (int j = 0; j < 8; ++j) {
                oacc[j][half * 2] *= alpha;
                oacc[j][half * 2 + 1] *= alpha;
            }
        }

#pragma unroll
        for (int kc = 0; kc < 8; ++kc) {
            uint32_t pa[4] = { ph[kc * 2][0], ph[kc * 2][1], ph[kc * 2 + 1][0], ph[kc * 2 + 1][1] };
#pragma unroll
            for (int dp = 0; dp < 4; ++dp) {
                uint32_t b[4];
                int row = kc * 16 + ((lane >> 3) & 1) * 8 + (lane & 7);
                int col = dp * 16 + (lane >> 4) * 8;
                ldmx4t(b[0], b[1], b[2], b[3], s2u(asmem + ATT_V + aidx(row, col)));
                mma_f16(oacc[dp * 2 + 0], pa, b[0], b[1]);
                mma_f16(oacc[dp * 2 + 1], pa, b[2], b[3]);
            }
        }
    }

#pragma unroll
    for (int half = 0; half < 2; ++half) {
        const float inv = 1.f / lrow[half];
        const int r = warp * 16 + (lane >> 2) + half * 8;
        const int n = __ldg(order + qbase + r);
        __half* dh = obhi + (size_t)n * C + h * HD;
#pragma unroll
        for (int j = 0; j < 8; ++j) {
            const int d0 = j * 8 + 2 * (lane & 3);
            *(uint32_t*)(dh + d0) = h2u(__floats2half2_rn(oacc[j][half * 2] * inv,
                                                          oacc[j][half * 2 + 1] * inv));
        }
    }
}

// ---------------- launch ----------------
extern "C" void kernel_launch(void* const* d_in, const int* in_sizes, int n_in,
                              void* d_out, int out_size)
{
    const float* feat      = (const float*)d_in[0];
    const int*   nbr       = (const int*)d_in[1];
    const int*   order     = (const int*)d_in[2];
    const float* cpe_w     = (const float*)d_in[3];
    const float* cpe_b     = (const float*)d_in[4];
    const float* cpe_lin_w = (const float*)d_in[5];
    const float* cpe_lin_b = (const float*)d_in[6];
    const float* cpe_ln_g  = (const float*)d_in[7];
    const float* cpe_ln_b  = (const float*)d_in[8];
    const float* ln1_g     = (const float*)d_in[9];
    const float* ln1_b     = (const float*)d_in[10];
    const float* qkv_w     = (const float*)d_in[11];
    const float* qkv_b     = (const float*)d_in[12];
    const float* proj_w    = (const float*)d_in[13];
    const float* proj_b    = (const float*)d_in[14];
    const float* ln2_g     = (const float*)d_in[15];
    const float* ln2_b     = (const float*)d_in[16];
    const float* fc1_w     = (const float*)d_in[17];
    const float* fc1_b     = (const float*)d_in[18];
    const float* fc2_w     = (const float*)d_in[19];
    const float* fc2_b     = (const float*)d_in[20];
    float* out = (float*)d_out;

    float *tmp1, *tmp2, *feat1;
    __half *wh, *fhi, *t1hi, *xhi, *qkvh, *obhi, *yhi, *stage;
    cudaGetSymbolAddress((void**)&tmp1,  g_tmp1);
    cudaGetSymbolAddress((void**)&tmp2,  g_tmp2);
    cudaGetSymbolAddress((void**)&feat1, g_feat1);
    cudaGetSymbolAddress((void**)&wh,    g_wh);
    cudaGetSymbolAddress((void**)&fhi,   g_fhi);
    cudaGetSymbolAddress((void**)&t1hi,  g_t1hi);
    cudaGetSymbolAddress((void**)&xhi,   g_xhi);
    cudaGetSymbolAddress((void**)&qkvh,  g_qkvh);
    cudaGetSymbolAddress((void**)&obhi,  g_obhi);
    cudaGetSymbolAddress((void**)&yhi,   g_yhi);
    cudaGetSymbolAddress((void**)&stage, g_stage);

    cudaFuncSetAttribute(tc_gemm<false,false,true,false>,  cudaFuncAttributeMaxDynamicSharedMemorySize, SMEM_BYTES);
    cudaFuncSetAttribute(tc_gemm<false,false,false,true>,  cudaFuncAttributeMaxDynamicSharedMemorySize, SMEM_BYTES);
    cudaFuncSetAttribute(tc_gemm<false,true,true,false>,   cudaFuncAttributeMaxDynamicSharedMemorySize, SMEM_BYTES);
    cudaFuncSetAttribute(tc_gemm<true,false,false,true>,   cudaFuncAttributeMaxDynamicSharedMemorySize, SMEM_BYTES);
    cudaFuncSetAttribute(cpe_sparse,  cudaFuncAttributeMaxDynamicSharedMemorySize, SMEM_BYTES);
    cudaFuncSetAttribute(attn_kernel, cudaFuncAttributeMaxDynamicSharedMemorySize, ATT_SMEM);

    // 1) fused prepass
    prep_all<<<10945, 256>>>(cpe_w, cpe_lin_w, qkv_w, proj_w, fc1_w, fc2_w, feat);
    // 2) sparse CPE prepass
    prep_count<<<dim3(NPTS / 256, 26), 256>>>(nbr);
    prep_scan<<<1, 128>>>();
    prep_fill<<<dim3(NPTS / 256, 26), 256>>>(nbr);

    const int MB = NPTS / 128;
    // 3) CPE center (dense, writes bias) -> tmp1; sparse taps -> stage; reduce -> t1hi
    tc_gemm<false,false,true,false><<<dim3(C/128, MB), 256, SMEM_BYTES>>>(
        fhi, wh + OFF_CPE + (size_t)13*C*C, cpe_b, nullptr, tmp1, nullptr, C, C);
    cpe_sparse<<<dim3(C/128, 160), 256, SMEM_BYTES>>>(fhi, wh + OFF_CPE, stage);
    cpe_reduce<<<NPTS, 128>>>(tmp1, stage, t1hi);
    // 4) cpe_lin -> tmp2
    tc_gemm<false,false,true,false><<<dim3(C/128, MB), 256, SMEM_BYTES>>>(
        t1hi, wh + OFF_LIN, cpe_lin_b, nullptr, tmp2, nullptr, C, C);
    // 5) feat1 = feat + LN(tmp2)
    ln_kernel<true,false><<<NPTS, 128>>>(tmp2, feat, cpe_ln_g, cpe_ln_b, feat1, nullptr);
    // 6) x = LN(feat1) -> fp16
    ln_kernel<false,true><<<NPTS, 128>>>(feat1, nullptr, ln1_g, ln1_b, nullptr, xhi);
    // 7) qkv
    tc_gemm<false,false,false,true><<<dim3(3*C/128, MB), 256, SMEM_BYTES>>>(
        xhi, wh + OFF_QKV, qkv_b, nullptr, nullptr, qkvh, 3*C, C);
    // 8) attention
    attn_kernel<<<dim3(KWIN/128, H, P), 256, ATT_SMEM>>>(qkvh, order, obhi);
    // 9) feat2 = feat1 + proj(ob) -> tmp1
    tc_gemm<false,true,true,false><<<dim3(C/128, MB), 256, SMEM_BYTES>>>(
        obhi, wh + OFF_PROJ, proj_b, feat1, tmp1, nullptr, C, C);
    // 10) x = LN(feat2) -> fp16
    ln_kernel<false,true><<<NPTS, 128>>>(tmp1, nullptr, ln2_g, ln2_b, nullptr, xhi);
    // 11) y = gelu(fc1(x)) -> fp16
    tc_gemm<true,false,false,true><<<dim3(4*C/128, MB), 256, SMEM_BYTES>>>(
        xhi, wh + OFF_FC1, fc1_b, nullptr, nullptr, yhi, 4*C, C);
    // 12) out = feat2 + fc2(y)
    tc_gemm<false,true,true,false><<<dim3(C/128, MB), 256, SMEM_BYTES>>>(
        yhi, wh + OFF_FC2, fc2_b, tmp1, out, nullptr, C, 4*C);
}

// round 8
// speedup vs baseline: 1.7546x; 1.0755x over previous
#include <cuda_runtime.h>
#include <cuda_fp16.h>
#include <math.h>
#include <stdint.h>

#define NPTS 16384
#define C 512
#define H 8
#define HD 64
#define KWIN 1024
#define P (NPTS / KWIN)
#define SCALE 0.125f
#define MAX_TAPS 26
#define NPERS 296   // persistent CTAs (2 per SM x 148)

// ---------------- scratch ----------------
__device__ float g_tmp1[NPTS * C];
__device__ float g_tmp2[NPTS * C];
__device__ float g_feat1[NPTS * C];

__device__ __half g_fhi[NPTS * C];
__device__ __half g_t1hi[NPTS * C];
__device__ __half g_xhi[NPTS * C];
__device__ __half g_qkvh[NPTS * 3 * C];
__device__ __half g_obhi[NPTS * C];
__device__ __half g_yhi[NPTS * 4 * C];
__device__ __half g_stage[(size_t)MAX_TAPS * NPTS * C];  // staging, row = s*NPTS + pos

#define WPOOL (27*C*C + C*C + 3*C*C + C*C + 4*C*C + 4*C*C)
__device__ __half g_wh[WPOOL];

#define OFF_CPE   0
#define OFF_LIN   (27*C*C)
#define OFF_QKV   (OFF_LIN + C*C)
#define OFF_PROJ  (OFF_QKV + 3*C*C)
#define OFF_FC1   (OFF_PROJ + C*C)
#define OFF_FC2   (OFF_FC1 + 4*C*C)

// sparse CPE bookkeeping (fixed-capacity tap regions)
__device__ int g_cursor[26];
__device__ int2 g_plist[MAX_TAPS * NPTS];
__device__ int g_pcnt[NPTS];
__device__ int g_prows[NPTS * MAX_TAPS];

// ---------------- helpers ----------------
__device__ __forceinline__ uint32_t s2u(const void* p) {
    return (uint32_t)__cvta_generic_to_shared(p);
}
__device__ __forceinline__ void ldmx4(uint32_t& r0, uint32_t& r1, uint32_t& r2, uint32_t& r3,
                                      uint32_t addr) {
    asm volatile("ldmatrix.sync.aligned.m8n8.x4.shared.b16 {%0,%1,%2,%3}, [%4];"
                 : "=r"(r0), "=r"(r1), "=r"(r2), "=r"(r3) : "r"(addr));
}
__device__ __forceinline__ void ldmx4t(uint32_t& r0, uint32_t& r1, uint32_t& r2, uint32_t& r3,
                                       uint32_t addr) {
    asm volatile("ldmatrix.sync.aligned.m8n8.x4.trans.shared.b16 {%0,%1,%2,%3}, [%4];"
                 : "=r"(r0), "=r"(r1), "=r"(r2), "=r"(r3) : "r"(addr));
}
__device__ __forceinline__ void mma_f16(float* d, const uint32_t* a, uint32_t b0, uint32_t b1) {
    asm volatile("mma.sync.aligned.m16n8k16.row.col.f32.f16.f16.f32 "
                 "{%0,%1,%2,%3},{%4,%5,%6,%7},{%8,%9},{%0,%1,%2,%3};"
                 : "+f"(d[0]), "+f"(d[1]), "+f"(d[2]), "+f"(d[3])
                 : "r"(a[0]), "r"(a[1]), "r"(a[2]), "r"(a[3]), "r"(b0), "r"(b1));
}
__device__ __forceinline__ int sidx(int r, int k) {
    return r * 32 + ((((k >> 3) ^ ((r >> 1) & 3)) << 3) | (k & 7));
}
__device__ __forceinline__ int aidx(int r, int k) {
    return r * 64 + ((((k >> 3) ^ (r & 7)) << 3) | (k & 7));
}
__device__ __forceinline__ uint32_t h2u(__half2 h) { return *(uint32_t*)&h; }
__device__ __forceinline__ uint4 cvt8s(float4 f0, float4 f1) {
    __half2 a = __floats2half2_rn(f0.x, f0.y), b = __floats2half2_rn(f0.z, f0.w);
    __half2 c = __floats2half2_rn(f1.x, f1.y), d = __floats2half2_rn(f1.z, f1.w);
    return make_uint4(h2u(a), h2u(b), h2u(c), h2u(d));
}

// GEMM smem: stage = A(4096) + B(4096) halves
#define ST_STRIDE 8192
#define SM_A 0
#define SM_B 4096
#define SMEM_BYTES (2 * ST_STRIDE * 2)

// ---------------- fused prepass ----------------
__global__ void prep_all(const float* __restrict__ w_cpe, const float* __restrict__ w_lin,
                         const float* __restrict__ w_qkv, const float* __restrict__ w_proj,
                         const float* __restrict__ w_fc1, const float* __restrict__ w_fc2,
                         const float* __restrict__ feat)
{
    const int b = blockIdx.x, t = threadIdx.x;
    if (b < 5120) {
        const int i = b * 2048 + t * 8;
        const float* s; int o;
        if (i < OFF_LIN)       { s = w_cpe;  o = i; }
        else if (i < OFF_QKV)  { s = w_lin;  o = i - OFF_LIN; }
        else if (i < OFF_PROJ) { s = w_qkv;  o = i - OFF_QKV; }
        else if (i < OFF_FC1)  { s = w_proj; o = i - OFF_PROJ; }
        else if (i < OFF_FC2)  { s = w_fc1;  o = i - OFF_FC1; }
        else                   { s = w_fc2;  o = i - OFF_FC2; }
        float4 f0 = *(const float4*)(s + o);
        float4 f1 = *(const float4*)(s + o + 4);
        *(uint4*)(g_wh + i) = cvt8s(f0, f1);
    } else if (b < 9216) {
        const int i = (b - 5120) * 2048 + t * 8;
        float4 f0 = *(const float4*)(feat + i);
        float4 f1 = *(const float4*)(feat + i + 4);
        *(uint4*)(g_fhi + i) = cvt8s(f0, f1);
    } else if (b < 9280) {
        g_pcnt[(b - 9216) * 256 + t] = 0;
    } else {
        if (t < 26) g_cursor[t] = 0;
    }
}

// ---------------- single-pass sparse fill ----------------
__global__ void prep_fill(const int* __restrict__ nbr)
{
    int s = blockIdx.y, kk = (s < 13) ? s : s + 1;
    int n = blockIdx.x * blockDim.x + threadIdx.x;
    int j = __ldg(nbr + (size_t)n * 27 + kk);
    bool v = j >= 0;
    unsigned m = __ballot_sync(0xffffffffu, v);
    int base = 0;
    if ((threadIdx.x & 31) == 0 && m) base = atomicAdd(&g_cursor[s], __popc(m));
    base = __shfl_sync(0xffffffffu, base, 0);
    if (v) {
        int pos = base + __popc(m & ((1u << (threadIdx.x & 31)) - 1));
        int srow = s * NPTS + pos;
        g_plist[srow] = make_int2(n, j);
        int slot = atomicAdd(&g_pcnt[n], 1);
        g_prows[n * MAX_TAPS + slot] = srow;
    }
}

// ---------------- core mma on one resident chunk ----------------
__device__ __forceinline__ void mma_chunk(const __half* sbuf, int wm, int wn, int lane,
                                          float acc[4][4][4])
{
#pragma unroll
    for (int kk16 = 0; kk16 < 2; ++kk16) {
        const int kc = kk16 * 2 + (lane >> 4);
        uint32_t aa[4][4], bb[2][4];
#pragma unroll
        for (int mf = 0; mf < 4; ++mf) {
            const int row = wm * 64 + mf * 16 + (lane & 15);
            ldmx4(aa[mf][0], aa[mf][1], aa[mf][2], aa[mf][3],
                  s2u(sbuf + SM_A + sidx(row, kc * 8)));
        }
#pragma unroll
        for (int np = 0; np < 2; ++np) {
            const int row = wn * 32 + np * 16 + (lane & 15);
            ldmx4(bb[np][0], bb[np][1], bb[np][2], bb[np][3],
                  s2u(sbuf + SM_B + sidx(row, kc * 8)));
        }
#pragma unroll
        for (int mf = 0; mf < 4; ++mf) {
#pragma unroll
            for (int nf = 0; nf < 4; ++nf) {
                const int pr = nf >> 1, sb = nf & 1;
                mma_f16(acc[mf][nf], aa[mf], bb[pr][sb], bb[pr][sb + 2]);
            }
        }
    }
}

// ---------------- epilogue ----------------
template <bool GELU, bool RES, bool WF32, bool WHI>
__device__ __forceinline__ void epilogue(float acc[4][4][4], int bm, int bn, int Nn,
                                         int wm, int wn, int lane,
                                         const float* bias, const float* res,
                                         float* outf, __half* outhi)
{
#pragma unroll
    for (int mf = 0; mf < 4; ++mf) {
#pragma unroll
        for (int nf = 0; nf < 4; ++nf) {
            const int n0 = bn + wn * 32 + nf * 8 + 2 * (lane & 3);
            const float b0 = __ldg(bias + n0), b1 = __ldg(bias + n0 + 1);
#pragma unroll
            for (int half = 0; half < 2; ++half) {
                const int m = bm + wm * 64 + mf * 16 + (lane >> 2) + half * 8;
                float v0 = acc[mf][nf][half * 2 + 0] + b0;
                float v1 = acc[mf][nf][half * 2 + 1] + b1;
                if (GELU) {
                    v0 = 0.5f * v0 * (1.f + erff(v0 * 0.70710678118f));
                    v1 = 0.5f * v1 * (1.f + erff(v1 * 0.70710678118f));
                }
                if (RES) {
                    float2 r2 = *(const float2*)(res + (size_t)m * Nn + n0);
                    v0 += r2.x; v1 += r2.y;
                }
                if (WF32)
                    *(float2*)(outf + (size_t)m * Nn + n0) = make_float2(v0, v1);
                if (WHI)
                    *(uint32_t*)(outhi + (size_t)m * Nn + n0) = h2u(__floats2half2_rn(v0, v1));
            }
        }
    }
}

// ---------------- persistent dense GEMM ----------------
template <bool GELU, bool RES, bool WF32, bool WHI>
__global__ void __launch_bounds__(256)
tc_gemm(const __half* __restrict__ Ah, const __half* __restrict__ Bh,
        const float* __restrict__ bias, const float* __restrict__ res,
        float* __restrict__ outf, __half* __restrict__ outhi,
        int Nn, int Kk)
{
    extern __shared__ __align__(16) __half smem[];
    const int t = threadIdx.x, lane = t & 31, warp = t >> 5;
    const int wm = warp >> 2, wn = warp & 3;
    const int nbn = Nn / 128;
    const int ntile = nbn * (NPTS / 128);
    const int nchunk = Kk / 32;
    const int r0 = t >> 2, c0 = t & 3;
    const int r1 = (t + 256) >> 2;

    for (int idx = blockIdx.x; idx < ntile; idx += gridDim.x) {
        const int bn = (idx % nbn) * 128, bm = (idx / nbn) * 128;
        float acc[4][4][4];
#pragma unroll
        for (int a = 0; a < 4; ++a)
#pragma unroll
            for (int b = 0; b < 4; ++b)
#pragma unroll
                for (int c = 0; c < 4; ++c) acc[a][b][c] = 0.f;

        const size_t a0 = (size_t)(bm + r0) * Kk + c0 * 8;
        const size_t a1 = (size_t)(bm + r1) * Kk + c0 * 8;
        const size_t b0 = (size_t)(bn + r0) * Kk + c0 * 8;
        const size_t b1 = (size_t)(bn + r1) * Kk + c0 * 8;

        *(uint4*)(smem + SM_A + sidx(r0, c0 * 8)) = *(const uint4*)(Ah + a0);
        *(uint4*)(smem + SM_A + sidx(r1, c0 * 8)) = *(const uint4*)(Ah + a1);
        *(uint4*)(smem + SM_B + sidx(r0, c0 * 8)) = *(const uint4*)(Bh + b0);
        *(uint4*)(smem + SM_B + sidx(r1, c0 * 8)) = *(const uint4*)(Bh + b1);
        __syncthreads();

        for (int chunk = 0; chunk < nchunk; ++chunk) {
            const __half* cur = smem + (chunk & 1) * ST_STRIDE;
            __half* nxt = smem + ((chunk + 1) & 1) * ST_STRIDE;
            uint4 pa0, pa1, pb0, pb1;
            const bool more = (chunk + 1 < nchunk);
            if (more) {
                const int kb = (chunk + 1) * 32;
                pa0 = *(const uint4*)(Ah + a0 + kb);
                pa1 = *(const uint4*)(Ah + a1 + kb);
                pb0 = *(const uint4*)(Bh + b0 + kb);
                pb1 = *(const uint4*)(Bh + b1 + kb);
            }
            mma_chunk(cur, wm, wn, lane, acc);
            __syncthreads();
            if (more) {
                *(uint4*)(nxt + SM_A + sidx(r0, c0 * 8)) = pa0;
                *(uint4*)(nxt + SM_A + sidx(r1, c0 * 8)) = pa1;
                *(uint4*)(nxt + SM_B + sidx(r0, c0 * 8)) = pb0;
                *(uint4*)(nxt + SM_B + sidx(r1, c0 * 8)) = pb1;
            }
            __syncthreads();
        }
        epilogue<GELU, RES, WF32, WHI>(acc, bm, bn, Nn, wm, wn, lane, bias, res, outf, outhi);
    }
}

// ---------------- sparse CPE GEMM: on-the-fly tile map, staged fp16 out ----------------
__global__ void __launch_bounds__(256)
cpe_sparse(const __half* __restrict__ fhi, const __half* __restrict__ W,
           __half* __restrict__ stage)
{
    extern __shared__ __align__(16) __half smem[];
    __shared__ int scnt[26], sofs[27];
    const int t = threadIdx.x, lane = t & 31, warp = t >> 5;
    const int wm = warp >> 2, wn = warp & 3;
    const int bn = blockIdx.x * 128;
    const int r0 = t >> 2, c0 = t & 3;
    const int r1 = (t + 256) >> 2;

    if (t < 26) scnt[t] = g_cursor[t];
    __syncthreads();
    if (t == 0) {
        int o = 0;
        for (int s = 0; s < 26; ++s) { sofs[s] = o; o += (scnt[s] + 127) >> 7; }
        sofs[26] = o;
    }
    __syncthreads();
    const int ntiles = sofs[26];

    for (int gt = blockIdx.y; gt < ntiles; gt += gridDim.y) {
        int s = 0;
        while (!(gt >= sofs[s] && gt < sofs[s + 1])) ++s;
        const int lt = gt - sofs[s];
        const int cnt = scnt[s];
        const int kk = (s < 13) ? s : s + 1;
        const __half* Wk = W + (size_t)kk * C * C;
        const int rowbase = s * NPTS + lt * 128;
        const int2* pl = g_plist + rowbase;

        float acc[4][4][4];
#pragma unroll
        for (int a = 0; a < 4; ++a)
#pragma unroll
            for (int b = 0; b < 4; ++b)
#pragma unroll
                for (int c = 0; c < 4; ++c) acc[a][b][c] = 0.f;

        const bool v0 = (lt * 128 + r0) < cnt, v1 = (lt * 128 + r1) < cnt;
        const int j0 = v0 ? __ldg(&pl[r0].y) : -1;
        const int j1 = v1 ? __ldg(&pl[r1].y) : -1;
        const size_t f0 = (size_t)(j0 < 0 ? 0 : j0) * C + c0 * 8;
        const size_t f1 = (size_t)(j1 < 0 ? 0 : j1) * C + c0 * 8;
        const uint4 zz = make_uint4(0, 0, 0, 0);

        *(uint4*)(smem + SM_A + sidx(r0, c0 * 8)) = (j0 >= 0) ? *(const uint4*)(fhi + f0) : zz;
        *(uint4*)(smem + SM_A + sidx(r1, c0 * 8)) = (j1 >= 0) ? *(const uint4*)(fhi + f1) : zz;
        *(uint4*)(smem + SM_B + sidx(r0, c0 * 8)) = *(const uint4*)(Wk + (size_t)(bn + r0) * C + c0 * 8);
        *(uint4*)(smem + SM_B + sidx(r1, c0 * 8)) = *(const uint4*)(Wk + (size_t)(bn + r1) * C + c0 * 8);
        __syncthreads();

        const int nchunk = C / 32;
        for (int chunk = 0; chunk < nchunk; ++chunk) {
            const __half* cur = smem + (chunk & 1) * ST_STRIDE;
            __half* nxt = smem + ((chunk + 1) & 1) * ST_STRIDE;
            uint4 pa0, pa1, pb0, pb1;
            const bool more = (chunk + 1 < nchunk);
            if (more) {
                const int kb = (chunk + 1) * 32;
                pa0 = (j0 >= 0) ? *(const uint4*)(fhi + f0 + kb) : zz;
                pa1 = (j1 >= 0) ? *(const uint4*)(fhi + f1 + kb) : zz;
                pb0 = *(const uint4*)(Wk + (size_t)(bn + r0) * C + kb + c0 * 8);
                pb1 = *(const uint4*)(Wk + (size_t)(bn + r1) * C + kb + c0 * 8);
            }
            mma_chunk(cur, wm, wn, lane, acc);
            __syncthreads();
            if (more) {
                *(uint4*)(nxt + SM_A + sidx(r0, c0 * 8)) = pa0;
                *(uint4*)(nxt + SM_A + sidx(r1, c0 * 8)) = pa1;
                *(uint4*)(nxt + SM_B + sidx(r0, c0 * 8)) = pb0;
                *(uint4*)(nxt + SM_B + sidx(r1, c0 * 8)) = pb1;
            }
            __syncthreads();
        }
#pragma unroll
        for (int mf = 0; mf < 4; ++mf) {
#pragma unroll
            for (int half = 0; half < 2; ++half) {
                const int ml = wm * 64 + mf * 16 + (lane >> 2) + half * 8;
                __half* dst = stage + (size_t)(rowbase + ml) * C;
#pragma unroll
                for (int nf = 0; nf < 4; ++nf) {
                    const int n0 = bn + wn * 32 + nf * 8 + 2 * (lane & 3);
                    *(uint32_t*)(dst + n0) =
                        h2u(__floats2half2_rn(acc[mf][nf][half * 2 + 0],
                                              acc[mf][nf][half * 2 + 1]));
                }
            }
        }
    }
}

// ---------------- gather-reduce ----------------
__global__ void cpe_reduce(const float* __restrict__ tmp1, const __half* __restrict__ stage,
                           __half* __restrict__ t1hi)
{
    const int n = blockIdx.x, t = threadIdx.x;
    const int c4 = t * 4;
    float4 v = *(const float4*)(tmp1 + (size_t)n * C + c4);
    const int cnt = g_pcnt[n];
    for (int i = 0; i < cnt; ++i) {
        const int srow = g_prows[n * MAX_TAPS + i];
        uint2 d = *(const uint2*)(stage + (size_t)srow * C + c4);
        float2 f0 = __half22float2(*(__half2*)&d.x);
        float2 f1 = __half22float2(*(__half2*)&d.y);
        v.x += f0.x; v.y += f0.y; v.z += f1.x; v.w += f1.y;
    }
    __half2 h0 = __floats2half2_rn(v.x, v.y);
    __half2 h1 = __floats2half2_rn(v.z, v.w);
    *(uint2*)(t1hi + (size_t)n * C + c4) = make_uint2(h2u(h0), h2u(h1));
}

// ---------------- LayerNorm helpers ----------------
__device__ __forceinline__ void block_stats(float4 v, int t, float& mean, float& inv)
{
    float s1 = v.x + v.y + v.z + v.w;
    float s2 = v.x * v.x + v.y * v.y + v.z * v.z + v.w * v.w;
#pragma unroll
    for (int o = 16; o; o >>= 1) {
        s1 += __shfl_xor_sync(0xffffffffu, s1, o);
        s2 += __shfl_xor_sync(0xffffffffu, s2, o);
    }
    __shared__ float sh1[4], sh2[4];
    const int wid = t >> 5, lane = t & 31;
    if (lane == 0) { sh1[wid] = s1; sh2[wid] = s2; }
    __syncthreads();
    float S1 = sh1[0] + sh1[1] + sh1[2] + sh1[3];
    float S2 = sh2[0] + sh2[1] + sh2[2] + sh2[3];
    mean = S1 * (1.f / C);
    float var = S2 * (1.f / C) - mean * mean;
    inv = rsqrtf(var + 1e-5f);
    __syncthreads();
}

// fused: feat1 = feat + LN(tmp2)*g1+b1 ; xhi = fp16(LN(feat1)*g2+b2)
__global__ void ln_cpe(const float* __restrict__ tmp2, const float* __restrict__ feat,
                       const float* __restrict__ g1, const float* __restrict__ b1,
                       const float* __restrict__ g2, const float* __restrict__ b2,
                       float* __restrict__ feat1, __half* __restrict__ xhi)
{
    const int n = blockIdx.x, t = threadIdx.x;
    float4 v = *(const float4*)(tmp2 + (size_t)n * C + t * 4);
    float mean, inv;
    block_stats(v, t, mean, inv);
    float4 gg = *(const float4*)(g1 + t * 4);
    float4 bb = *(const float4*)(b1 + t * 4);
    float4 fr = *(const float4*)(feat + (size_t)n * C + t * 4);
    float4 w;
    w.x = fr.x + (v.x - mean) * inv * gg.x + bb.x;
    w.y = fr.y + (v.y - mean) * inv * gg.y + bb.y;
    w.z = fr.z + (v.z - mean) * inv * gg.z + bb.z;
    w.w = fr.w + (v.w - mean) * inv * gg.w + bb.w;
    *(float4*)(feat1 + (size_t)n * C + t * 4) = w;

    float mean2, inv2;
    block_stats(w, t, mean2, inv2);
    float4 g4 = *(const float4*)(g2 + t * 4);
    float4 b4 = *(const float4*)(b2 + t * 4);
    __half2 h0 = __floats2half2_rn((w.x - mean2) * inv2 * g4.x + b4.x,
                                   (w.y - mean2) * inv2 * g4.y + b4.y);
    __half2 h1 = __floats2half2_rn((w.z - mean2) * inv2 * g4.z + b4.z,
                                   (w.w - mean2) * inv2 * g4.w + b4.w);
    *(uint2*)(xhi + (size_t)n * C + t * 4) = make_uint2(h2u(h0), h2u(h1));
}

// plain LN -> fp16
__global__ void ln_h16(const float* __restrict__ in,
                       const float* __restrict__ gam, const float* __restrict__ bet,
                       __half* __restrict__ outhi)
{
    const int n = blockIdx.x, t = threadIdx.x;
    float4 v = *(const float4*)(in + (size_t)n * C + t * 4);
    float mean, inv;
    block_stats(v, t, mean, inv);
    float4 g4 = *(const float4*)(gam + t * 4);
    float4 b4 = *(const float4*)(bet + t * 4);
    __half2 h0 = __floats2half2_rn((v.x - mean) * inv * g4.x + b4.x,
                                   (v.y - mean) * inv * g4.y + b4.y);
    __half2 h1 = __floats2half2_rn((v.z - mean) * inv * g4.z + b4.z,
                                   (v.w - mean) * inv * g4.w + b4.w);
    *(uint2*)(outhi + (size_t)n * C + t * 4) = make_uint2(h2u(h0), h2u(h1));
}

// ---------------- tensor-core flash attention (KV tile 64, 2 CTA/SM) ----------------
#define ATT_Q 0
#define ATT_K 8192
#define ATT_V 12288
#define ATT_SMEM (16384 * 2)

__global__ void __launch_bounds__(256, 2)
attn_kernel(const __half* __restrict__ qkvh, const int* __restrict__ order,
            __half* __restrict__ obhi)
{
    extern __shared__ __align__(16) __half asmem[];
    const int t = threadIdx.x, lane = t & 31, warp = t >> 5;
    const int qt = blockIdx.x, h = blockIdx.y, p = blockIdx.z;
    const int qbase = p * KWIN + qt * 128;
    const __half2 hsc = __floats2half2_rn(SCALE, SCALE);

    for (int u = t; u < 1024; u += 256) {
        int r = u >> 3, c = u & 7;
        int n = __ldg(order + qbase + r);
        uint4 q = *(const uint4*)(qkvh + (size_t)n * (3 * C) + h * HD + c * 8);
        __half2* qh = (__half2*)&q;
        qh[0] = __hmul2(qh[0], hsc); qh[1] = __hmul2(qh[1], hsc);
        qh[2] = __hmul2(qh[2], hsc); qh[3] = __hmul2(qh[3], hsc);
        *(uint4*)(asmem + ATT_Q + aidx(r, c * 8)) = q;
    }

    float mrow[2] = {-1e30f, -1e30f}, lrow[2] = {0.f, 0.f};
    float oacc[8][4];
#pragma unroll
    for (int j = 0; j < 8; ++j)
#pragma unroll
        for (int c = 0; c < 4; ++c) oacc[j][c] = 0.f;

    for (int kt = 0; kt < KWIN / 64; ++kt) {
        __syncthreads();
        for (int u = t; u < 512; u += 256) {
            int r = u >> 3, c = u & 7;
            int n = __ldg(order + p * KWIN + kt * 64 + r);
            *(uint4*)(asmem + ATT_K + aidx(r, c * 8)) =
                *(const uint4*)(qkvh + (size_t)n * (3 * C) + C + h * HD + c * 8);
            *(uint4*)(asmem + ATT_V + aidx(r, c * 8)) =
                *(const uint4*)(qkvh + (size_t)n * (3 * C) + 2 * C + h * HD + c * 8);
        }
        __syncthreads();

        float s[8][4];
#pragma unroll
        for (int j = 0; j < 8; ++j)
#pragma unroll
            for (int c = 0; c < 4; ++c) s[j][c] = 0.f;
#pragma unroll
        for (int kk = 0; kk < 4; ++kk) {
            const int kc = kk * 2 + (lane >> 4);
            uint32_t a[4];
            {
                int row = warp * 16 + (lane & 15);
                ldmx4(a[0], a[1], a[2], a[3], s2u(asmem + ATT_Q + aidx(row, kc * 8)));
            }
#pragma unroll
            for (int np = 0; np < 4; ++np) {
                uint32_t b[4];
                int row = np * 16 + (lane & 15);
                ldmx4(b[0], b[1], b[2], b[3], s2u(asmem + ATT_K + aidx(row, kc * 8)));
                mma_f16(s[np * 2 + 0], a, b[0], b[2]);
                mma_f16(s[np * 2 + 1], a, b[1], b[3]);
            }
        }

        uint32_t ph[8][2];
#pragma unroll
        for (int half = 0; half < 2; ++half) {
            float mx = mrow[half];
#pragma unroll
            for (int j = 0; j < 8; ++j)
                mx = fmaxf(mx, fmaxf(s[j][half * 2], s[j][half * 2 + 1]));
            mx = fmaxf(mx, __shfl_xor_sync(0xffffffffu, mx, 1));
            mx = fmaxf(mx, __shfl_xor_sync(0xffffffffu, mx, 2));
            const float alpha = __expf(mrow[half] - mx);
            float sum = 0.f;
#pragma unroll
            for (int j = 0; j < 8; ++j) {
                __half2 e = h2exp2(__floats2half2_rn(
                    (s[j][half * 2] - mx) * 1.44269504f,
                    (s[j][half * 2 + 1] - mx) * 1.44269504f));
                ph[j][half] = h2u(e);
                float2 f = __half22float2(e);
                sum += f.x + f.y;
            }
            sum += __shfl_xor_sync(0xffffffffu, sum, 1);
            sum += __shfl_xor_sync(0xffffffffu, sum, 2);
            lrow[half] = lrow[half] * alpha + sum;
            mrow[half] = mx;
#pragma unroll
            for (int j = 0; j < 8; ++j) {
                oacc[j][half * 2] *= alpha;
                oacc[j][half * 2 + 1] *= alpha;
            }
        }

#pragma unroll
        for (int kc = 0; kc < 4; ++kc) {
            uint32_t pa[4] = { ph[kc * 2][0], ph[kc * 2][1], ph[kc * 2 + 1][0], ph[kc * 2 + 1][1] };
#pragma unroll
            for (int dp = 0; dp < 4; ++dp) {
                uint32_t b[4];
                int row = kc * 16 + ((lane >> 3) & 1) * 8 + (lane & 7);
                int col = dp * 16 + (lane >> 4) * 8;
                ldmx4t(b[0], b[1], b[2], b[3], s2u(asmem + ATT_V + aidx(row, col)));
                mma_f16(oacc[dp * 2 + 0], pa, b[0], b[1]);
                mma_f16(oacc[dp * 2 + 1], pa, b[2], b[3]);
            }
        }
    }

#pragma unroll
    for (int half = 0; half < 2; ++half) {
        const float inv = 1.f / lrow[half];
        const int r = warp * 16 + (lane >> 2) + half * 8;
        const int n = __ldg(order + qbase + r);
        __half* dh = obhi + (size_t)n * C + h * HD;
#pragma unroll
        for (int j = 0; j < 8; ++j) {
            const int d0 = j * 8 + 2 * (lane & 3);
            *(uint32_t*)(dh + d0) = h2u(__floats2half2_rn(oacc[j][half * 2] * inv,
                                                          oacc[j][half * 2 + 1] * inv));
        }
    }
}

// ---------------- launch ----------------
extern "C" void kernel_launch(void* const* d_in, const int* in_sizes, int n_in,
                              void* d_out, int out_size)
{
    const float* feat      = (const float*)d_in[0];
    const int*   nbr       = (const int*)d_in[1];
    const int*   order     = (const int*)d_in[2];
    const float* cpe_w     = (const float*)d_in[3];
    const float* cpe_b     = (const float*)d_in[4];
    const float* cpe_lin_w = (const float*)d_in[5];
    const float* cpe_lin_b = (const float*)d_in[6];
    const float* cpe_ln_g  = (const float*)d_in[7];
    const float* cpe_ln_b  = (const float*)d_in[8];
    const float* ln1_g     = (const float*)d_in[9];
    const float* ln1_b     = (const float*)d_in[10];
    const float* qkv_w     = (const float*)d_in[11];
    const float* qkv_b     = (const float*)d_in[12];
    const float* proj_w    = (const float*)d_in[13];
    const float* proj_b    = (const float*)d_in[14];
    const float* ln2_g     = (const float*)d_in[15];
    const float* ln2_b     = (const float*)d_in[16];
    const float* fc1_w     = (const float*)d_in[17];
    const float* fc1_b     = (const float*)d_in[18];
    const float* fc2_w     = (const float*)d_in[19];
    const float* fc2_b     = (const float*)d_in[20];
    float* out = (float*)d_out;

    float *tmp1, *tmp2, *feat1;
    __half *wh, *fhi, *t1hi, *xhi, *qkvh, *obhi, *yhi, *stage;
    cudaGetSymbolAddress((void**)&tmp1,  g_tmp1);
    cudaGetSymbolAddress((void**)&tmp2,  g_tmp2);
    cudaGetSymbolAddress((void**)&feat1, g_feat1);
    cudaGetSymbolAddress((void**)&wh,    g_wh);
    cudaGetSymbolAddress((void**)&fhi,   g_fhi);
    cudaGetSymbolAddress((void**)&t1hi,  g_t1hi);
    cudaGetSymbolAddress((void**)&xhi,   g_xhi);
    cudaGetSymbolAddress((void**)&qkvh,  g_qkvh);
    cudaGetSymbolAddress((void**)&obhi,  g_obhi);
    cudaGetSymbolAddress((void**)&yhi,   g_yhi);
    cudaGetSymbolAddress((void**)&stage, g_stage);

    cudaFuncSetAttribute(tc_gemm<false,false,true,false>,  cudaFuncAttributeMaxDynamicSharedMemorySize, SMEM_BYTES);
    cudaFuncSetAttribute(tc_gemm<false,false,false,true>,  cudaFuncAttributeMaxDynamicSharedMemorySize, SMEM_BYTES);
    cudaFuncSetAttribute(tc_gemm<false,true,true,false>,   cudaFuncAttributeMaxDynamicSharedMemorySize, SMEM_BYTES);
    cudaFuncSetAttribute(tc_gemm<true,false,false,true>,   cudaFuncAttributeMaxDynamicSharedMemorySize, SMEM_BYTES);
    cudaFuncSetAttribute(cpe_sparse,  cudaFuncAttributeMaxDynamicSharedMemorySize, SMEM_BYTES);
    cudaFuncSetAttribute(attn_kernel, cudaFuncAttributeMaxDynamicSharedMemorySize, ATT_SMEM);

    // 1) fused prepass (weights fp16, feat fp16, pcnt/cursor zero)
    prep_all<<<9281, 256>>>(cpe_w, cpe_lin_w, qkv_w, proj_w, fc1_w, fc2_w, feat);
    // 2) single-pass sparse fill
    prep_fill<<<dim3(NPTS / 256, 26), 256>>>(nbr);

    // 3) CPE center dense -> tmp1; sparse taps -> stage; reduce -> t1hi
    tc_gemm<false,false,true,false><<<NPERS, 256, SMEM_BYTES>>>(
        fhi, wh + OFF_CPE + (size_t)13*C*C, cpe_b, nullptr, tmp1, nullptr, C, C);
    cpe_sparse<<<dim3(C/128, 160), 256, SMEM_BYTES>>>(fhi, wh + OFF_CPE, stage);
    cpe_reduce<<<NPTS, 128>>>(tmp1, stage, t1hi);
    // 4) cpe_lin -> tmp2
    tc_gemm<false,false,true,false><<<NPERS, 256, SMEM_BYTES>>>(
        t1hi, wh + OFF_LIN, cpe_lin_b, nullptr, tmp2, nullptr, C, C);
    // 5+6) fused: feat1 = feat + LN(tmp2); xhi = fp16(LN(feat1))
    ln_cpe<<<NPTS, 128>>>(tmp2, feat, cpe_ln_g, cpe_ln_b, ln1_g, ln1_b, feat1, xhi);
    // 7) qkv
    tc_gemm<false,false,false,true><<<NPERS, 256, SMEM_BYTES>>>(
        xhi, wh + OFF_QKV, qkv_b, nullptr, nullptr, qkvh, 3*C, C);
    // 8) attention
    attn_kernel<<<dim3(KWIN/128, H, P), 256, ATT_SMEM>>>(qkvh, order, obhi);
    // 9) feat2 = feat1 + proj(ob) -> tmp1
    tc_gemm<false,true,true,false><<<NPERS, 256, SMEM_BYTES>>>(
        obhi, wh + OFF_PROJ, proj_b, feat1, tmp1, nullptr, C, C);
    // 10) x = LN(feat2) -> fp16
    ln_h16<<<NPTS, 128>>>(tmp1, ln2_g, ln2_b, xhi);
    // 11) y = gelu(fc1(x)) -> fp16
    tc_gemm<true,false,false,true><<<NPERS, 256, SMEM_BYTES>>>(
        xhi, wh + OFF_FC1, fc1_b, nullptr, nullptr, yhi, 4*C, C);
    // 12) out = feat2 + fc2(y)
    tc_gemm<false,true,true,false><<<NPERS, 256, SMEM_BYTES>>>(
        yhi, wh + OFF_FC2, fc2_b, tmp1, out, nullptr, C, 4*C);
}

// round 9
// speedup vs baseline: 1.9791x; 1.1280x over previous
#include <cuda_runtime.h>
#include <cuda_fp16.h>
#include <math.h>
#include <stdint.h>

#define NPTS 16384
#define C 512
#define H 8
#define HD 64
#define KWIN 1024
#define P (NPTS / KWIN)
#define SCALE 0.125f
#define MAX_TAPS 26
#define NPERS 296

// ---------------- scratch ----------------
__device__ float g_tmp1[NPTS * C];
__device__ float g_tmp2[NPTS * C];
__device__ float g_feat1[NPTS * C];

__device__ __half g_fhi[NPTS * C];
__device__ __half g_t1hi[NPTS * C];
__device__ __half g_xhi[NPTS * C];
__device__ __half g_qkvh[NPTS * 3 * C];
__device__ __half g_obhi[NPTS * C];
__device__ __half g_yhi[NPTS * 4 * C];
__device__ __half g_stage[(size_t)MAX_TAPS * NPTS * C];

#define WPOOL (27*C*C + C*C + 3*C*C + C*C + 4*C*C + 4*C*C)
__device__ __half g_wh[WPOOL];

#define OFF_CPE   0
#define OFF_LIN   (27*C*C)
#define OFF_QKV   (OFF_LIN + C*C)
#define OFF_PROJ  (OFF_QKV + 3*C*C)
#define OFF_FC1   (OFF_PROJ + C*C)
#define OFF_FC2   (OFF_FC1 + 4*C*C)

// sparse CPE bookkeeping
__device__ int g_cursor[26];
__device__ int2 g_plist[MAX_TAPS * NPTS];
__device__ int g_pcnt[NPTS];
__device__ int g_prows[NPTS * MAX_TAPS];

// ---------------- helpers ----------------
__device__ __forceinline__ uint32_t s2u(const void* p) {
    return (uint32_t)__cvta_generic_to_shared(p);
}
__device__ __forceinline__ void ldmx4(uint32_t& r0, uint32_t& r1, uint32_t& r2, uint32_t& r3,
                                      uint32_t addr) {
    asm volatile("ldmatrix.sync.aligned.m8n8.x4.shared.b16 {%0,%1,%2,%3}, [%4];"
                 : "=r"(r0), "=r"(r1), "=r"(r2), "=r"(r3) : "r"(addr));
}
__device__ __forceinline__ void ldmx4t(uint32_t& r0, uint32_t& r1, uint32_t& r2, uint32_t& r3,
                                       uint32_t addr) {
    asm volatile("ldmatrix.sync.aligned.m8n8.x4.trans.shared.b16 {%0,%1,%2,%3}, [%4];"
                 : "=r"(r0), "=r"(r1), "=r"(r2), "=r"(r3) : "r"(addr));
}
__device__ __forceinline__ void mma_f16(float* d, const uint32_t* a, uint32_t b0, uint32_t b1) {
    asm volatile("mma.sync.aligned.m16n8k16.row.col.f32.f16.f16.f32 "
                 "{%0,%1,%2,%3},{%4,%5,%6,%7},{%8,%9},{%0,%1,%2,%3};"
                 : "+f"(d[0]), "+f"(d[1]), "+f"(d[2]), "+f"(d[3])
                 : "r"(a[0]), "r"(a[1]), "r"(a[2]), "r"(a[3]), "r"(b0), "r"(b1));
}
__device__ __forceinline__ void cpa16(uint32_t dst, const void* src, int srcsize) {
    asm volatile("cp.async.cg.shared.global [%0], [%1], 16, %2;"
                 :: "r"(dst), "l"(src), "r"(srcsize) : "memory");
}
__device__ __forceinline__ void cpa_commit() {
    asm volatile("cp.async.commit_group;" ::: "memory");
}
template <int N>
__device__ __forceinline__ void cpa_wait() {
    asm volatile("cp.async.wait_group %0;" :: "n"(N) : "memory");
}
// swizzled index for [128][64]-half tiles (128B rows)
__device__ __forceinline__ int aidx(int r, int k) {
    return r * 64 + ((((k >> 3) ^ (r & 7)) << 3) | (k & 7));
}
__device__ __forceinline__ uint32_t h2u(__half2 h) { return *(uint32_t*)&h; }
__device__ __forceinline__ uint4 cvt8s(float4 f0, float4 f1) {
    __half2 a = __floats2half2_rn(f0.x, f0.y), b = __floats2half2_rn(f0.z, f0.w);
    __half2 c = __floats2half2_rn(f1.x, f1.y), d = __floats2half2_rn(f1.z, f1.w);
    return make_uint4(h2u(a), h2u(b), h2u(c), h2u(d));
}

// GEMM smem: stage = A(128x64) + B(128x64) halves, 3 stages
#define CH 64
#define STG 3
#define STA 0
#define STB 8192
#define STAGE_H 16384
#define SMEM_BYTES (STG * STAGE_H * 2)   // 98304

// ---------------- fused prepass ----------------
__global__ void prep_all(const float* __restrict__ w_cpe, const float* __restrict__ w_lin,
                         const float* __restrict__ w_qkv, const float* __restrict__ w_proj,
                         const float* __restrict__ w_fc1, const float* __restrict__ w_fc2,
                         const float* __restrict__ feat)
{
    const int b = blockIdx.x, t = threadIdx.x;
    if (b < 5120) {
        const int i = b * 2048 + t * 8;
        const float* s; int o;
        if (i < OFF_LIN)       { s = w_cpe;  o = i; }
        else if (i < OFF_QKV)  { s = w_lin;  o = i - OFF_LIN; }
        else if (i < OFF_PROJ) { s = w_qkv;  o = i - OFF_QKV; }
        else if (i < OFF_FC1)  { s = w_proj; o = i - OFF_PROJ; }
        else if (i < OFF_FC2)  { s = w_fc1;  o = i - OFF_FC1; }
        else                   { s = w_fc2;  o = i - OFF_FC2; }
        float4 f0 = *(const float4*)(s + o);
        float4 f1 = *(const float4*)(s + o + 4);
        *(uint4*)(g_wh + i) = cvt8s(f0, f1);
    } else if (b < 9216) {
        const int i = (b - 5120) * 2048 + t * 8;
        float4 f0 = *(const float4*)(feat + i);
        float4 f1 = *(const float4*)(feat + i + 4);
        *(uint4*)(g_fhi + i) = cvt8s(f0, f1);
    } else if (b < 9280) {
        g_pcnt[(b - 9216) * 256 + t] = 0;
    } else {
        if (t < 26) g_cursor[t] = 0;
    }
}

// ---------------- single-pass sparse fill ----------------
__global__ void prep_fill(const int* __restrict__ nbr)
{
    int s = blockIdx.y, kk = (s < 13) ? s : s + 1;
    int n = blockIdx.x * blockDim.x + threadIdx.x;
    int j = __ldg(nbr + (size_t)n * 27 + kk);
    bool v = j >= 0;
    unsigned m = __ballot_sync(0xffffffffu, v);
    int base = 0;
    if ((threadIdx.x & 31) == 0 && m) base = atomicAdd(&g_cursor[s], __popc(m));
    base = __shfl_sync(0xffffffffu, base, 0);
    if (v) {
        int pos = base + __popc(m & ((1u << (threadIdx.x & 31)) - 1));
        int srow = s * NPTS + pos;
        g_plist[srow] = make_int2(n, j);
        int slot = atomicAdd(&g_pcnt[n], 1);
        g_prows[n * MAX_TAPS + slot] = srow;
    }
}

// ---------------- stage loaders (cp.async) ----------------
__device__ __forceinline__ void load_dense(__half* buf, const __half* Ah, const __half* Bh,
                                           int bm, int bn, int Kk, int kb, int t)
{
#pragma unroll
    for (int i = 0; i < 4; ++i) {
        const int idx = t + i * 256;
        const int r = idx >> 3, c = idx & 7;
        cpa16(s2u(buf + STA + aidx(r, c * 8)), Ah + (size_t)(bm + r) * Kk + kb + c * 8, 16);
        cpa16(s2u(buf + STB + aidx(r, c * 8)), Bh + (size_t)(bn + r) * Kk + kb + c * 8, 16);
    }
    cpa_commit();
}
__device__ __forceinline__ void load_sparse(__half* buf, const __half* fhi, const __half* Wk,
                                            const int* sj, int bn, int kb, int t)
{
#pragma unroll
    for (int i = 0; i < 4; ++i) {
        const int idx = t + i * 256;
        const int r = idx >> 3, c = idx & 7;
        const int j = sj[r];
        const int sz = (j >= 0) ? 16 : 0;
        const __half* src = fhi + (size_t)(j < 0 ? 0 : j) * C + kb + c * 8;
        cpa16(s2u(buf + STA + aidx(r, c * 8)), src, sz);
        cpa16(s2u(buf + STB + aidx(r, c * 8)), Wk + (size_t)(bn + r) * C + kb + c * 8, 16);
    }
    cpa_commit();
}

// ---------------- mma on one resident K=64 chunk ----------------
__device__ __forceinline__ void mma_chunk64(const __half* sbuf, int wm, int wn, int lane,
                                            float acc[4][4][4])
{
#pragma unroll
    for (int kk16 = 0; kk16 < 4; ++kk16) {
        const int kc = kk16 * 2 + (lane >> 4);
        uint32_t aa[4][4], bb[2][4];
#pragma unroll
        for (int mf = 0; mf < 4; ++mf) {
            const int row = wm * 64 + mf * 16 + (lane & 15);
            ldmx4(aa[mf][0], aa[mf][1], aa[mf][2], aa[mf][3],
                  s2u(sbuf + STA + aidx(row, kc * 8)));
        }
#pragma unroll
        for (int np = 0; np < 2; ++np) {
            const int row = wn * 32 + np * 16 + (lane & 15);
            ldmx4(bb[np][0], bb[np][1], bb[np][2], bb[np][3],
                  s2u(sbuf + STB + aidx(row, kc * 8)));
        }
#pragma unroll
        for (int mf = 0; mf < 4; ++mf) {
#pragma unroll
            for (int nf = 0; nf < 4; ++nf) {
                const int pr = nf >> 1, sb = nf & 1;
                mma_f16(acc[mf][nf], aa[mf], bb[pr][sb], bb[pr][sb + 2]);
            }
        }
    }
}

// ---------------- epilogue ----------------
template <bool GELU, bool RES, bool WF32, bool WHI>
__device__ __forceinline__ void epilogue(float acc[4][4][4], int bm, int bn, int Nn,
                                         int wm, int wn, int lane,
                                         const float* bias, const float* res,
                                         float* outf, __half* outhi)
{
#pragma unroll
    for (int mf = 0; mf < 4; ++mf) {
#pragma unroll
        for (int nf = 0; nf < 4; ++nf) {
            const int n0 = bn + wn * 32 + nf * 8 + 2 * (lane & 3);
            const float b0 = __ldg(bias + n0), b1 = __ldg(bias + n0 + 1);
#pragma unroll
            for (int half = 0; half < 2; ++half) {
                const int m = bm + wm * 64 + mf * 16 + (lane >> 2) + half * 8;
                float v0 = acc[mf][nf][half * 2 + 0] + b0;
                float v1 = acc[mf][nf][half * 2 + 1] + b1;
                if (GELU) {
                    v0 = 0.5f * v0 * (1.f + erff(v0 * 0.70710678118f));
                    v1 = 0.5f * v1 * (1.f + erff(v1 * 0.70710678118f));
                }
                if (RES) {
                    float2 r2 = *(const float2*)(res + (size_t)m * Nn + n0);
                    v0 += r2.x; v1 += r2.y;
                }
                if (WF32)
                    *(float2*)(outf + (size_t)m * Nn + n0) = make_float2(v0, v1);
                if (WHI)
                    *(uint32_t*)(outhi + (size_t)m * Nn + n0) = h2u(__floats2half2_rn(v0, v1));
            }
        }
    }
}

// ---------------- persistent dense GEMM (cp.async 3-stage) ----------------
template <bool GELU, bool RES, bool WF32, bool WHI>
__global__ void __launch_bounds__(256)
tc_gemm(const __half* __restrict__ Ah, const __half* __restrict__ Bh,
        const float* __restrict__ bias, const float* __restrict__ res,
        float* __restrict__ outf, __half* __restrict__ outhi,
        int Nn, int Kk)
{
    extern __shared__ __align__(16) __half smem[];
    const int t = threadIdx.x, lane = t & 31, warp = t >> 5;
    const int wm = warp >> 2, wn = warp & 3;
    const int nbn = Nn / 128;
    const int ntile = nbn * (NPTS / 128);
    const int nchunk = Kk / CH;

    for (int idx = blockIdx.x; idx < ntile; idx += gridDim.x) {
        const int bn = (idx % nbn) * 128, bm = (idx / nbn) * 128;
        __syncthreads();   // protect stage buffers from previous tile's readers
        load_dense(smem, Ah, Bh, bm, bn, Kk, 0, t);
        load_dense(smem + STAGE_H, Ah, Bh, bm, bn, Kk, CH, t);

        float acc[4][4][4];
#pragma unroll
        for (int a = 0; a < 4; ++a)
#pragma unroll
            for (int b = 0; b < 4; ++b)
#pragma unroll
                for (int c = 0; c < 4; ++c) acc[a][b][c] = 0.f;

        for (int ck = 0; ck < nchunk; ++ck) {
            if (ck + 2 < nchunk) cpa_wait<1>(); else cpa_wait<0>();
            __syncthreads();
            if (ck + 2 < nchunk)
                load_dense(smem + ((ck + 2) % STG) * STAGE_H, Ah, Bh, bm, bn, Kk,
                           (ck + 2) * CH, t);
            mma_chunk64(smem + (ck % STG) * STAGE_H, wm, wn, lane, acc);
        }
        epilogue<GELU, RES, WF32, WHI>(acc, bm, bn, Nn, wm, wn, lane, bias, res, outf, outhi);
    }
}

// ---------------- sparse CPE GEMM (cp.async + zfill gather) ----------------
__global__ void __launch_bounds__(256)
cpe_sparse(const __half* __restrict__ fhi, const __half* __restrict__ W,
           __half* __restrict__ stage)
{
    extern __shared__ __align__(16) __half smem[];
    __shared__ int scnt[26], sofs[27], sj[128];
    const int t = threadIdx.x, lane = t & 31, warp = t >> 5;
    const int wm = warp >> 2, wn = warp & 3;
    const int bn = blockIdx.x * 128;
    const int nchunk = C / CH;

    if (t < 26) scnt[t] = g_cursor[t];
    __syncthreads();
    if (t == 0) {
        int o = 0;
        for (int s = 0; s < 26; ++s) { sofs[s] = o; o += (scnt[s] + 127) >> 7; }
        sofs[26] = o;
    }
    __syncthreads();
    const int ntiles = sofs[26];

    for (int gt = blockIdx.y; gt < ntiles; gt += gridDim.y) {
        int s = 0;
        while (!(gt >= sofs[s] && gt < sofs[s + 1])) ++s;
        const int lt = gt - sofs[s];
        const int cnt = scnt[s];
        const int kk = (s < 13) ? s : s + 1;
        const __half* Wk = W + (size_t)kk * C * C;
        const int rowbase = s * NPTS + lt * 128;
        const int2* pl = g_plist + rowbase;

        __syncthreads();   // protect sj + stage buffers from previous tile
        if (t < 128) {
            const bool v = (lt * 128 + t) < cnt;
            sj[t] = v ? pl[t].y : -1;
        }
        __syncthreads();

        load_sparse(smem, fhi, Wk, sj, bn, 0, t);
        load_sparse(smem + STAGE_H, fhi, Wk, sj, bn, CH, t);

        float acc[4][4][4];
#pragma unroll
        for (int a = 0; a < 4; ++a)
#pragma unroll
            for (int b = 0; b < 4; ++b)
#pragma unroll
                for (int c = 0; c < 4; ++c) acc[a][b][c] = 0.f;

        for (int ck = 0; ck < nchunk; ++ck) {
            if (ck + 2 < nchunk) cpa_wait<1>(); else cpa_wait<0>();
            __syncthreads();
            if (ck + 2 < nchunk)
                load_sparse(smem + ((ck + 2) % STG) * STAGE_H, fhi, Wk, sj, bn,
                            (ck + 2) * CH, t);
            mma_chunk64(smem + (ck % STG) * STAGE_H, wm, wn, lane, acc);
        }

        // staged fp16 store (padded rows harmless; never read)
#pragma unroll
        for (int mf = 0; mf < 4; ++mf) {
#pragma unroll
            for (int half = 0; half < 2; ++half) {
                const int ml = wm * 64 + mf * 16 + (lane >> 2) + half * 8;
                __half* dst = stage + (size_t)(rowbase + ml) * C;
#pragma unroll
                for (int nf = 0; nf < 4; ++nf) {
                    const int n0 = bn + wn * 32 + nf * 8 + 2 * (lane & 3);
                    *(uint32_t*)(dst + n0) =
                        h2u(__floats2half2_rn(acc[mf][nf][half * 2 + 0],
                                              acc[mf][nf][half * 2 + 1]));
                }
            }
        }
    }
}

// ---------------- gather-reduce ----------------
__global__ void cpe_reduce(const float* __restrict__ tmp1, const __half* __restrict__ stage,
                           __half* __restrict__ t1hi)
{
    const int n = blockIdx.x, t = threadIdx.x;
    const int c4 = t * 4;
    float4 v = *(const float4*)(tmp1 + (size_t)n * C + c4);
    const int cnt = g_pcnt[n];
    for (int i = 0; i < cnt; ++i) {
        const int srow = g_prows[n * MAX_TAPS + i];
        uint2 d = *(const uint2*)(stage + (size_t)srow * C + c4);
        float2 f0 = __half22float2(*(__half2*)&d.x);
        float2 f1 = __half22float2(*(__half2*)&d.y);
        v.x += f0.x; v.y += f0.y; v.z += f1.x; v.w += f1.y;
    }
    __half2 h0 = __floats2half2_rn(v.x, v.y);
    __half2 h1 = __floats2half2_rn(v.z, v.w);
    *(uint2*)(t1hi + (size_t)n * C + c4) = make_uint2(h2u(h0), h2u(h1));
}

// ---------------- LayerNorm helpers ----------------
__device__ __forceinline__ void block_stats(float4 v, int t, float& mean, float& inv)
{
    float s1 = v.x + v.y + v.z + v.w;
    float s2 = v.x * v.x + v.y * v.y + v.z * v.z + v.w * v.w;
#pragma unroll
    for (int o = 16; o; o >>= 1) {
        s1 += __shfl_xor_sync(0xffffffffu, s1, o);
        s2 += __shfl_xor_sync(0xffffffffu, s2, o);
    }
    __shared__ float sh1[4], sh2[4];
    const int wid = t >> 5, lane = t & 31;
    if (lane == 0) { sh1[wid] = s1; sh2[wid] = s2; }
    __syncthreads();
    float S1 = sh1[0] + sh1[1] + sh1[2] + sh1[3];
    float S2 = sh2[0] + sh2[1] + sh2[2] + sh2[3];
    mean = S1 * (1.f / C);
    float var = S2 * (1.f / C) - mean * mean;
    inv = rsqrtf(var + 1e-5f);
    __syncthreads();
}

__global__ void ln_cpe(const float* __restrict__ tmp2, const float* __restrict__ feat,
                       const float* __restrict__ g1, const float* __restrict__ b1,
                       const float* __restrict__ g2, const float* __restrict__ b2,
                       float* __restrict__ feat1, __half* __restrict__ xhi)
{
    const int n = blockIdx.x, t = threadIdx.x;
    float4 v = *(const float4*)(tmp2 + (size_t)n * C + t * 4);
    float mean, inv;
    block_stats(v, t, mean, inv);
    float4 gg = *(const float4*)(g1 + t * 4);
    float4 bb = *(const float4*)(b1 + t * 4);
    float4 fr = *(const float4*)(feat + (size_t)n * C + t * 4);
    float4 w;
    w.x = fr.x + (v.x - mean) * inv * gg.x + bb.x;
    w.y = fr.y + (v.y - mean) * inv * gg.y + bb.y;
    w.z = fr.z + (v.z - mean) * inv * gg.z + bb.z;
    w.w = fr.w + (v.w - mean) * inv * gg.w + bb.w;
    *(float4*)(feat1 + (size_t)n * C + t * 4) = w;

    float mean2, inv2;
    block_stats(w, t, mean2, inv2);
    float4 g4 = *(const float4*)(g2 + t * 4);
    float4 b4 = *(const float4*)(b2 + t * 4);
    __half2 h0 = __floats2half2_rn((w.x - mean2) * inv2 * g4.x + b4.x,
                                   (w.y - mean2) * inv2 * g4.y + b4.y);
    __half2 h1 = __floats2half2_rn((w.z - mean2) * inv2 * g4.z + b4.z,
                                   (w.w - mean2) * inv2 * g4.w + b4.w);
    *(uint2*)(xhi + (size_t)n * C + t * 4) = make_uint2(h2u(h0), h2u(h1));
}

__global__ void ln_h16(const float* __restrict__ in,
                       const float* __restrict__ gam, const float* __restrict__ bet,
                       __half* __restrict__ outhi)
{
    const int n = blockIdx.x, t = threadIdx.x;
    float4 v = *(const float4*)(in + (size_t)n * C + t * 4);
    float mean, inv;
    block_stats(v, t, mean, inv);
    float4 g4 = *(const float4*)(gam + t * 4);
    float4 b4 = *(const float4*)(bet + t * 4);
    __half2 h0 = __floats2half2_rn((v.x - mean) * inv * g4.x + b4.x,
                                   (v.y - mean) * inv * g4.y + b4.y);
    __half2 h1 = __floats2half2_rn((v.z - mean) * inv * g4.z + b4.z,
                                   (v.w - mean) * inv * g4.w + b4.w);
    *(uint2*)(outhi + (size_t)n * C + t * 4) = make_uint2(h2u(h0), h2u(h1));
}

// ---------------- tensor-core flash attention (KV tile 64, 2 CTA/SM) ----------------
#define ATT_Q 0
#define ATT_K 8192
#define ATT_V 12288
#define ATT_SMEM (16384 * 2)

__global__ void __launch_bounds__(256, 2)
attn_kernel(const __half* __restrict__ qkvh, const int* __restrict__ order,
            __half* __restrict__ obhi)
{
    extern __shared__ __align__(16) __half asmem[];
    const int t = threadIdx.x, lane = t & 31, warp = t >> 5;
    const int qt = blockIdx.x, h = blockIdx.y, p = blockIdx.z;
    const int qbase = p * KWIN + qt * 128;
    const __half2 hsc = __floats2half2_rn(SCALE, SCALE);

    for (int u = t; u < 1024; u += 256) {
        int r = u >> 3, c = u & 7;
        int n = __ldg(order + qbase + r);
        uint4 q = *(const uint4*)(qkvh + (size_t)n * (3 * C) + h * HD + c * 8);
        __half2* qh = (__half2*)&q;
        qh[0] = __hmul2(qh[0], hsc); qh[1] = __hmul2(qh[1], hsc);
        qh[2] = __hmul2(qh[2], hsc); qh[3] = __hmul2(qh[3], hsc);
        *(uint4*)(asmem + ATT_Q + aidx(r, c * 8)) = q;
    }

    float mrow[2] = {-1e30f, -1e30f}, lrow[2] = {0.f, 0.f};
    float oacc[8][4];
#pragma unroll
    for (int j = 0; j < 8; ++j)
#pragma unroll
        for (int c = 0; c < 4; ++c) oacc[j][c] = 0.f;

    for (int kt = 0; kt < KWIN / 64; ++kt) {
        __syncthreads();
        for (int u = t; u < 512; u += 256) {
            int r = u >> 3, c = u & 7;
            int n = __ldg(order + p * KWIN + kt * 64 + r);
            *(uint4*)(asmem + ATT_K + aidx(r, c * 8)) =
                *(const uint4*)(qkvh + (size_t)n * (3 * C) + C + h * HD + c * 8);
            *(uint4*)(asmem + ATT_V + aidx(r, c * 8)) =
                *(const uint4*)(qkvh + (size_t)n * (3 * C) + 2 * C + h * HD + c * 8);
        }
        __syncthreads();

        float s[8][4];
#pragma unroll
        for (int j = 0; j < 8; ++j)
#pragma unroll
            for (int c = 0; c < 4; ++c) s[j][c] = 0.f;
#pragma unroll
        for (int kk = 0; kk < 4; ++kk) {
            const int kc = kk * 2 + (lane >> 4);
            uint32_t a[4];
            {
                int row = warp * 16 + (lane & 15);
                ldmx4(a[0], a[1], a[2], a[3], s2u(asmem + ATT_Q + aidx(row, kc * 8)));
            }
#pragma unroll
            for (int np = 0; np < 4; ++np) {
                uint32_t b[4];
                int row = np * 16 + (lane & 15);
                ldmx4(b[0], b[1], b[2], b[3], s2u(asmem + ATT_K + aidx(row, kc * 8)));
                mma_f16(s[np * 2 + 0], a, b[0], b[2]);
                mma_f16(s[np * 2 + 1], a, b[1], b[3]);
            }
        }

        uint32_t ph[8][2];
#pragma unroll
        for (int half = 0; half < 2; ++half) {
            float mx = mrow[half];
#pragma unroll
            for (int j = 0; j < 8; ++j)
                mx = fmaxf(mx, fmaxf(s[j][half * 2], s[j][half * 2 + 1]));
            mx = fmaxf(mx, __shfl_xor_sync(0xffffffffu, mx, 1));
            mx = fmaxf(mx, __shfl_xor_sync(0xffffffffu, mx, 2));
            const float alpha = __expf(mrow[half] - mx);
            float sum = 0.f;
#pragma unroll
            for (int j = 0; j < 8; ++j) {
                __half2 e = h2exp2(__floats2half2_rn(
                    (s[j][half * 2] - mx) * 1.44269504f,
                    (s[j][half * 2 + 1] - mx) * 1.44269504f));
                ph[j][half] = h2u(e);
                float2 f = __half22float2(e);
                sum += f.x + f.y;
            }
            sum += __shfl_xor_sync(0xffffffffu, sum, 1);
            sum += __shfl_xor_sync(0xffffffffu, sum, 2);
            lrow[half] = lrow[half] * alpha + sum;
            mrow[half] = mx;
#pragma unroll
            for (int j = 0; j < 8; ++j) {
                oacc[j][half * 2] *= alpha;
                oacc[j][half * 2 + 1] *= alpha;
            }
        }

#pragma unroll
        for (int kc = 0; kc < 4; ++kc) {
            uint32_t pa[4] = { ph[kc * 2][0], ph[kc * 2][1], ph[kc * 2 + 1][0], ph[kc * 2 + 1][1] };
#pragma unroll
            for (int dp = 0; dp < 4; ++dp) {
                uint32_t b[4];
                int row = kc * 16 + ((lane >> 3) & 1) * 8 + (lane & 7);
                int col = dp * 16 + (lane >> 4) * 8;
                ldmx4t(b[0], b[1], b[2], b[3], s2u(asmem + ATT_V + aidx(row, col)));
                mma_f16(oacc[dp * 2 + 0], pa, b[0], b[1]);
                mma_f16(oacc[dp * 2 + 1], pa, b[2], b[3]);
            }
        }
    }

#pragma unroll
    for (int half = 0; half < 2; ++half) {
        const float inv = 1.f / lrow[half];
        const int r = warp * 16 + (lane >> 2) + half * 8;
        const int n = __ldg(order + qbase + r);
        __half* dh = obhi + (size_t)n * C + h * HD;
#pragma unroll
        for (int j = 0; j < 8; ++j) {
            const int d0 = j * 8 + 2 * (lane & 3);
            *(uint32_t*)(dh + d0) = h2u(__floats2half2_rn(oacc[j][half * 2] * inv,
                                                          oacc[j][half * 2 + 1] * inv));
        }
    }
}

// ---------------- launch ----------------
extern "C" void kernel_launch(void* const* d_in, const int* in_sizes, int n_in,
                              void* d_out, int out_size)
{
    const float* feat      = (const float*)d_in[0];
    const int*   nbr       = (const int*)d_in[1];
    const int*   order     = (const int*)d_in[2];
    const float* cpe_w     = (const float*)d_in[3];
    const float* cpe_b     = (const float*)d_in[4];
    const float* cpe_lin_w = (const float*)d_in[5];
    const float* cpe_lin_b = (const float*)d_in[6];
    const float* cpe_ln_g  = (const float*)d_in[7];
    const float* cpe_ln_b  = (const float*)d_in[8];
    const float* ln1_g     = (const float*)d_in[9];
    const float* ln1_b     = (const float*)d_in[10];
    const float* qkv_w     = (const float*)d_in[11];
    const float* qkv_b     = (const float*)d_in[12];
    const float* proj_w    = (const float*)d_in[13];
    const float* proj_b    = (const float*)d_in[14];
    const float* ln2_g     = (const float*)d_in[15];
    const float* ln2_b     = (const float*)d_in[16];
    const float* fc1_w     = (const float*)d_in[17];
    const float* fc1_b     = (const float*)d_in[18];
    const float* fc2_w     = (const float*)d_in[19];
    const float* fc2_b     = (const float*)d_in[20];
    float* out = (float*)d_out;

    float *tmp1, *tmp2, *feat1;
    __half *wh, *fhi, *t1hi, *xhi, *qkvh, *obhi, *yhi, *stage;
    cudaGetSymbolAddress((void**)&tmp1,  g_tmp1);
    cudaGetSymbolAddress((void**)&tmp2,  g_tmp2);
    cudaGetSymbolAddress((void**)&feat1, g_feat1);
    cudaGetSymbolAddress((void**)&wh,    g_wh);
    cudaGetSymbolAddress((void**)&fhi,   g_fhi);
    cudaGetSymbolAddress((void**)&t1hi,  g_t1hi);
    cudaGetSymbolAddress((void**)&xhi,   g_xhi);
    cudaGetSymbolAddress((void**)&qkvh,  g_qkvh);
    cudaGetSymbolAddress((void**)&obhi,  g_obhi);
    cudaGetSymbolAddress((void**)&yhi,   g_yhi);
    cudaGetSymbolAddress((void**)&stage, g_stage);

    cudaFuncSetAttribute(tc_gemm<false,false,true,false>,  cudaFuncAttributeMaxDynamicSharedMemorySize, SMEM_BYTES);
    cudaFuncSetAttribute(tc_gemm<false,false,false,true>,  cudaFuncAttributeMaxDynamicSharedMemorySize, SMEM_BYTES);
    cudaFuncSetAttribute(tc_gemm<false,true,true,false>,   cudaFuncAttributeMaxDynamicSharedMemorySize, SMEM_BYTES);
    cudaFuncSetAttribute(tc_gemm<true,false,false,true>,   cudaFuncAttributeMaxDynamicSharedMemorySize, SMEM_BYTES);
    cudaFuncSetAttribute(cpe_sparse,  cudaFuncAttributeMaxDynamicSharedMemorySize, SMEM_BYTES);
    cudaFuncSetAttribute(attn_kernel, cudaFuncAttributeMaxDynamicSharedMemorySize, ATT_SMEM);

    // 1) fused prepass
    prep_all<<<9281, 256>>>(cpe_w, cpe_lin_w, qkv_w, proj_w, fc1_w, fc2_w, feat);
    // 2) single-pass sparse fill
    prep_fill<<<dim3(NPTS / 256, 26), 256>>>(nbr);

    // 3) CPE center dense -> tmp1; sparse taps -> stage; reduce -> t1hi
    tc_gemm<false,false,true,false><<<NPERS, 256, SMEM_BYTES>>>(
        fhi, wh + OFF_CPE + (size_t)13*C*C, cpe_b, nullptr, tmp1, nullptr, C, C);
    cpe_sparse<<<dim3(C/128, 160), 256, SMEM_BYTES>>>(fhi, wh + OFF_CPE, stage);
    cpe_reduce<<<NPTS, 128>>>(tmp1, stage, t1hi);
    // 4) cpe_lin -> tmp2
    tc_gemm<false,false,true,false><<<NPERS, 256, SMEM_BYTES>>>(
        t1hi, wh + OFF_LIN, cpe_lin_b, nullptr, tmp2, nullptr, C, C);
    // 5) fused: feat1 = feat + LN(tmp2); xhi = fp16(LN(feat1))
    ln_cpe<<<NPTS, 128>>>(tmp2, feat, cpe_ln_g, cpe_ln_b, ln1_g, ln1_b, feat1, xhi);
    // 6) qkv
    tc_gemm<false,false,false,true><<<NPERS, 256, SMEM_BYTES>>>(
        xhi, wh + OFF_QKV, qkv_b, nullptr, nullptr, qkvh, 3*C, C);
    // 7) attention
    attn_kernel<<<dim3(KWIN/128, H, P), 256, ATT_SMEM>>>(qkvh, order, obhi);
    // 8) feat2 = feat1 + proj(ob) -> tmp1
    tc_gemm<false,true,true,false><<<NPERS, 256, SMEM_BYTES>>>(
        obhi, wh + OFF_PROJ, proj_b, feat1, tmp1, nullptr, C, C);
    // 9) x = LN(feat2) -> fp16
    ln_h16<<<NPTS, 128>>>(tmp1, ln2_g, ln2_b, xhi);
    // 10) y = gelu(fc1(x)) -> fp16
    tc_gemm<true,false,false,true><<<NPERS, 256, SMEM_BYTES>>>(
        xhi, wh + OFF_FC1, fc1_b, nullptr, nullptr, yhi, 4*C, C);
    // 11) out = feat2 + fc2(y)
    tc_gemm<false,true,true,false><<<NPERS, 256, SMEM_BYTES>>>(
        yhi, wh + OFF_FC2, fc2_b, tmp1, out, nullptr, C, 4*C);
}